// round 12
// baseline (speedup 1.0000x reference)
#include <cuda_runtime.h>
#include <cuda_bf16.h>
#include <math.h>
#include <stdint.h>

#define BB 4
#define TT 1024
#define DM 768
#define NHEAD 12
#define HDIM 64
#define NL 4
#define VV 50304
#define D3 2304
#define D4 3072
#define BT 4096   // B*T

typedef __nv_bfloat16 bf16;

// ---------------- scratch (device globals; no allocation anywhere) ----------------
__device__ float g_x  [BT * DM];
__device__ float g_a  [BT * D4];
__device__ float g_xf [BB * DM];
__device__ bf16 g_xn_h [BT * DM],  g_xn_l [BT * DM];
__device__ bf16 g_att_h[BT * DM],  g_att_l[BT * DM];
__device__ bf16 g_h_h  [BT * D4],  g_h_l  [BT * D4];
__device__ bf16 g_c2_h [BT * D4],  g_c2_l [BT * D4];
// split qkv activations
__device__ bf16 g_q_h[BT * DM], g_q_l[BT * DM];
__device__ bf16 g_k_h[BT * DM], g_k_l[BT * DM];
__device__ bf16 g_v_h[BT * DM], g_v_l[BT * DM];
// split-bf16 weights, all stored [N][K] (K contiguous)
__device__ bf16 g_wq_h[NL * D3 * DM], g_wq_l[NL * D3 * DM];
__device__ bf16 g_wp_h[NL * DM * DM], g_wp_l[NL * DM * DM];
__device__ bf16 g_wf_h[NL * D4 * DM], g_wf_l[NL * D4 * DM];
__device__ bf16 g_wW_h[NL * D4 * D4], g_wW_l[NL * D4 * D4];
__device__ bf16 g_wV_h[NL * D4 * D4], g_wV_l[NL * D4 * D4];
__device__ bf16 g_wm_h[NL * DM * D4], g_wm_l[NL * DM * D4];

// ================= asm helpers (base sm_103 features only) =================
__device__ __forceinline__ uint32_t smem_u32(const void* p) {
    uint32_t a;
    asm("{ .reg .u64 t; cvta.to.shared.u64 t, %1; cvt.u32.u64 %0, t; }" : "=r"(a) : "l"(p));
    return a;
}
#define SWZ(off) ((off) ^ (((off) >> 3) & 0x70))

#define CP16(dst, src) \
    asm volatile("cp.async.cg.shared.global [%0], [%1], 16;" :: "r"(dst), "l"(src) : "memory")
#define CP_COMMIT() asm volatile("cp.async.commit_group;" ::: "memory")
#define CP_WAIT1()  asm volatile("cp.async.wait_group 1;"  ::: "memory")
#define CP_WAIT0()  asm volatile("cp.async.wait_group 0;"  ::: "memory")

#define LDM4(r0, r1, r2, r3, addr) \
    asm volatile("ldmatrix.sync.aligned.m8n8.x4.shared.b16 {%0,%1,%2,%3}, [%4];" \
                 : "=r"(r0), "=r"(r1), "=r"(r2), "=r"(r3) : "r"(addr))

#define LDM4T(r0, r1, r2, r3, addr) \
    asm volatile("ldmatrix.sync.aligned.m8n8.x4.trans.shared.b16 {%0,%1,%2,%3}, [%4];" \
                 : "=r"(r0), "=r"(r1), "=r"(r2), "=r"(r3) : "r"(addr))

#define MMA(D, A, B) \
    asm volatile("mma.sync.aligned.m16n8k16.row.col.f32.bf16.bf16.f32 " \
                 "{%0,%1,%2,%3}, {%4,%5,%6,%7}, {%8,%9}, {%0,%1,%2,%3};" \
                 : "+f"((D)[0]), "+f"((D)[1]), "+f"((D)[2]), "+f"((D)[3]) \
                 : "r"((A)[0]), "r"((A)[1]), "r"((A)[2]), "r"((A)[3]), \
                   "r"((B)[0]), "r"((B)[1]))

__device__ __forceinline__ void split2_store(bf16* H, bf16* L, size_t off, float v0, float v1) {
    bf16 h0 = __float2bfloat16(v0), h1 = __float2bfloat16(v1);
    bf16 l0 = __float2bfloat16(v0 - __bfloat162float(h0));
    bf16 l1 = __float2bfloat16(v1 - __bfloat162float(h1));
    *(__nv_bfloat162*)(H + off) = __halves2bfloat162(h0, h1);
    *(__nv_bfloat162*)(L + off) = __halves2bfloat162(l0, l1);
}

__device__ __forceinline__ void splitpack(float x, float y, uint32_t& hi, uint32_t& lo) {
    bf16 xh = __float2bfloat16(x), yh = __float2bfloat16(y);
    bf16 xl = __float2bfloat16(x - __bfloat162float(xh));
    bf16 yl = __float2bfloat16(y - __bfloat162float(yh));
    hi = (uint32_t)__bfloat16_as_ushort(xh) | ((uint32_t)__bfloat16_as_ushort(yh) << 16);
    lo = (uint32_t)__bfloat16_as_ushort(xl) | ((uint32_t)__bfloat16_as_ushort(yl) << 16);
}

// ---------------- weight conversion ----------------
__global__ void split_all(const float* __restrict__ s0, bf16* h0, bf16* l0, int n0,
                          const float* __restrict__ s1, bf16* h1, bf16* l1, int n1,
                          const float* __restrict__ s2, bf16* h2, bf16* l2, int n2,
                          const float* __restrict__ s3, bf16* h3, bf16* l3, int n3) {
    const float* s; bf16 *h, *l; int n;
    switch (blockIdx.y) {
        case 0: s = s0; h = h0; l = l0; n = n0; break;
        case 1: s = s1; h = h1; l = l1; n = n1; break;
        case 2: s = s2; h = h2; l = l2; n = n2; break;
        default:s = s3; h = h3; l = l3; n = n3; break;
    }
    int i = blockIdx.x * blockDim.x + threadIdx.x;
    if (i >= n) return;
    float4 v = ((const float4*)s)[i];
    split2_store(h, l, (size_t)i * 4,     v.x, v.y);
    split2_store(h, l, (size_t)i * 4 + 2, v.z, v.w);
}

__global__ void transpose_all(const float* __restrict__ W, const float* __restrict__ V,
                              bf16* __restrict__ Wh, bf16* __restrict__ Wl,
                              bf16* __restrict__ Vh, bf16* __restrict__ Vl) {
    __shared__ float t[32][33];
    int z = blockIdx.z;
    int l = (z < NL) ? z : z - NL;
    const float* s = ((z < NL) ? W : V) + (size_t)l * D4 * D4;
    bf16* H = ((z < NL) ? Wh : Vh) + (size_t)l * D4 * D4;
    bf16* L = ((z < NL) ? Wl : Vl) + (size_t)l * D4 * D4;
    int n0 = blockIdx.x * 32, k0 = blockIdx.y * 32;
    int cx = threadIdx.x;
    #pragma unroll
    for (int r = threadIdx.y; r < 32; r += 8)
        t[r][cx] = s[(size_t)(k0 + r) * D4 + n0 + cx];
    __syncthreads();
    #pragma unroll
    for (int r = threadIdx.y; r < 32; r += 8) {
        float v = t[cx][r];
        size_t off = (size_t)(n0 + r) * D4 + k0 + cx;
        bf16 h = __float2bfloat16(v);
        H[off] = h;
        L[off] = __float2bfloat16(v - __bfloat162float(h));
    }
}

// ---------------- embedding ----------------
__global__ void embed_kernel(const int* __restrict__ idx, const float* __restrict__ wte,
                             const float* __restrict__ wpe, float* __restrict__ x) {
    int bt = blockIdx.x;
    int t  = bt & (TT - 1);
    int tok = idx[bt];
    int c = threadIdx.x * 4;
    float4 a = *(const float4*)&wte[(size_t)tok * DM + c];
    float4 p = *(const float4*)&wpe[(size_t)t   * DM + c];
    a.x += p.x; a.y += p.y; a.z += p.z; a.w += p.w;
    *(float4*)&x[(size_t)bt * DM + c] = a;
}

// ---------------- layernorm ----------------
template <bool SPLIT>
__global__ __launch_bounds__(256)
void ln_kernel(const float* __restrict__ x, size_t rstride,
               const float* __restrict__ w, const float* __restrict__ b,
               float* __restrict__ yf, bf16* __restrict__ yh, bf16* __restrict__ yl) {
    const float* xr = x + (size_t)blockIdx.x * rstride;
    int tid = threadIdx.x;

    float v0 = xr[tid], v1 = xr[tid + 256], v2 = xr[tid + 512];
    float s  = v0 + v1 + v2;
    float s2 = v0 * v0 + v1 * v1 + v2 * v2;
    #pragma unroll
    for (int off = 16; off; off >>= 1) {
        s  += __shfl_xor_sync(0xffffffffu, s,  off);
        s2 += __shfl_xor_sync(0xffffffffu, s2, off);
    }
    __shared__ float sh_s[8], sh_s2[8];
    int wid = tid >> 5, lane = tid & 31;
    if (lane == 0) { sh_s[wid] = s; sh_s2[wid] = s2; }
    __syncthreads();
    float tot = 0.f, tot2 = 0.f;
    #pragma unroll
    for (int i = 0; i < 8; i++) { tot += sh_s[i]; tot2 += sh_s2[i]; }
    const float inv = 1.0f / (float)DM;
    float mean = tot * inv;
    float var  = tot2 * inv - mean * mean;
    float rstd = rsqrtf(var + 1e-5f);

    size_t base = (size_t)blockIdx.x * DM;
    float o0 = (v0 - mean) * rstd * w[tid]       + b[tid];
    float o1 = (v1 - mean) * rstd * w[tid + 256] + b[tid + 256];
    float o2 = (v2 - mean) * rstd * w[tid + 512] + b[tid + 512];
    if (SPLIT) {
        bf16 h0 = __float2bfloat16(o0);
        yh[base + tid] = h0;       yl[base + tid]       = __float2bfloat16(o0 - __bfloat162float(h0));
        bf16 h1 = __float2bfloat16(o1);
        yh[base + tid + 256] = h1; yl[base + tid + 256] = __float2bfloat16(o1 - __bfloat162float(h1));
        bf16 h2 = __float2bfloat16(o2);
        yh[base + tid + 512] = h2; yl[base + tid + 512] = __float2bfloat16(o2 - __bfloat162float(h2));
    } else {
        yf[base + tid]       = o0;
        yf[base + tid + 256] = o1;
        yf[base + tid + 512] = o2;
    }
}

// ================= mma.sync split-bf16 GEMM (R8 config + GM_QKV epilogue) =========
#define GM_F32    0
#define GM_RES    1
#define GM_SPLIT  2
#define GM_SWIGLU 3
#define GM_QKV    4

#define GSTAGE 65536
#define GSMEM  (3 * GSTAGE + 1024)

struct Frags {
    uint32_t aH[2][4], aL[2][4], bH[8][2], bL[8][2];
};

template <int MODE>
__global__ __launch_bounds__(256, 1)
void gemm_mma(const bf16* __restrict__ Ah, const bf16* __restrict__ Al,
              const bf16* __restrict__ Bh, const bf16* __restrict__ Bl,
              const float* __restrict__ bias, const float* __restrict__ aux,
              float* __restrict__ Cf, bf16* __restrict__ Ch, bf16* __restrict__ Cl,
              int N, int K) {
    extern __shared__ char dyn[];
    uint32_t base = (smem_u32(dyn) + 1023) & ~1023u;

    const int tid = threadIdx.x;
    const int bm = blockIdx.y * 128, bn = blockIdx.x * 128;
    const int lane = tid & 31, wid = tid >> 5;
    const int wm = wid & 3, wn = wid >> 2;

    const int lr = ((lane >> 3) & 1) * 8 + (lane & 7);
    const int lk = lane >> 4;

    float d[2][8][4];
    #pragma unroll
    for (int i = 0; i < 2; i++)
        #pragma unroll
        for (int j = 0; j < 8; j++)
            #pragma unroll
            for (int q = 0; q < 4; q++) d[i][j][q] = 0.f;

    const int nkt = K >> 6;

    auto load_stage = [&](int kt, int sb) {
        uint32_t st = base + sb * GSTAGE;
        int k0 = kt << 6;
        #pragma unroll
        for (int i = 0; i < 4; i++) {
            int row = (tid >> 3) + i * 32;
            int seg = tid & 7;
            uint32_t soff = SWZ(row * 128 + seg * 16);
            size_t ga = (size_t)(bm + row) * K + k0 + seg * 8;
            size_t gb = (size_t)(bn + row) * K + k0 + seg * 8;
            CP16(st + soff,         Ah + ga);
            CP16(st + 16384 + soff, Al + ga);
            CP16(st + 32768 + soff, Bh + gb);
            CP16(st + 49152 + soff, Bl + gb);
        }
    };

    auto load_frags = [&](uint32_t st, int ks, Frags& f) {
        #pragma unroll
        for (int am = 0; am < 2; am++) {
            int row = wm * 32 + am * 16 + lr;
            uint32_t off = SWZ(row * 128 + (ks * 2 + lk) * 16);
            LDM4(f.aH[am][0], f.aH[am][1], f.aH[am][2], f.aH[am][3], st + off);
            LDM4(f.aL[am][0], f.aL[am][1], f.aL[am][2], f.aL[am][3], st + 16384 + off);
        }
        #pragma unroll
        for (int nb = 0; nb < 4; nb++) {
            int row = wn * 64 + nb * 16 + lr;
            uint32_t off = SWZ(row * 128 + (ks * 2 + lk) * 16);
            uint32_t t0, t1, t2, t3;
            LDM4(t0, t1, t2, t3, st + 32768 + off);
            f.bH[2*nb][0] = t0; f.bH[2*nb][1] = t2; f.bH[2*nb+1][0] = t1; f.bH[2*nb+1][1] = t3;
            LDM4(t0, t1, t2, t3, st + 49152 + off);
            f.bL[2*nb][0] = t0; f.bL[2*nb][1] = t2; f.bL[2*nb+1][0] = t1; f.bL[2*nb+1][1] = t3;
        }
    };
    auto do_mma = [&](Frags& f) {
        #pragma unroll
        for (int am = 0; am < 2; am++)
            #pragma unroll
            for (int an = 0; an < 8; an++) {
                MMA(d[am][an], f.aH[am], f.bH[an]);
                MMA(d[am][an], f.aH[am], f.bL[an]);
                MMA(d[am][an], f.aL[am], f.bH[an]);
            }
    };

    load_stage(0, 0); CP_COMMIT();
    load_stage(1, 1); CP_COMMIT();

    Frags fr[2];
    for (int kt = 0; kt < nkt; kt++) {
        CP_WAIT1();
        __syncthreads();
        if (kt + 2 < nkt) load_stage(kt + 2, (kt + 2) % 3);
        CP_COMMIT();

        uint32_t st = base + (kt % 3) * GSTAGE;
        load_frags(st, 0, fr[0]);
        #pragma unroll
        for (int ks = 0; ks < 4; ks++) {
            if (ks < 3) load_frags(st, ks + 1, fr[(ks + 1) & 1]);
            do_mma(fr[ks & 1]);
        }
    }

    const int g = lane >> 2, tq = lane & 3;
    #pragma unroll
    for (int am = 0; am < 2; am++)
        #pragma unroll
        for (int an = 0; an < 8; an++) {
            int r0 = bm + wm * 32 + am * 16 + g;
            int c  = bn + wn * 64 + an * 8 + tq * 2;
            #pragma unroll
            for (int half = 0; half < 2; half++) {
                int row = r0 + half * 8;
                float v0 = d[am][an][half * 2]     + bias[c];
                float v1 = d[am][an][half * 2 + 1] + bias[c + 1];
                size_t off = (size_t)row * N + c;
                if (MODE == GM_F32) {
                    *(float2*)(Cf + off) = make_float2(v0, v1);
                } else if (MODE == GM_RES) {
                    float2 o = *(const float2*)(Cf + off);
                    *(float2*)(Cf + off) = make_float2(v0 + o.x, v1 + o.y);
                } else if (MODE == GM_SPLIT) {
                    split2_store(Ch, Cl, off, v0, v1);
                } else if (MODE == GM_SWIGLU) {
                    float2 gg = *(const float2*)(aux + off);
                    float s0 = gg.x / (1.f + __expf(-gg.x));
                    float s1 = gg.y / (1.f + __expf(-gg.y));
                    split2_store(Ch, Cl, off, s0 * v0, s1 * v1);
                } else {  // GM_QKV: split-store into q/k/v buffers by column range
                    bf16 *H, *L; int cc;
                    if (c < DM)            { H = g_q_h; L = g_q_l; cc = c; }
                    else if (c < 2 * DM)   { H = g_k_h; L = g_k_l; cc = c - DM; }
                    else                   { H = g_v_h; L = g_v_l; cc = c - 2 * DM; }
                    split2_store(H, L, (size_t)row * DM + cc, v0, v1);
                }
            }
        }
}

// ---------------- SIMT sgemm (lm_head only, M=4) ----------------
__global__ __launch_bounds__(256)
void sgemm_kernel(const float* __restrict__ A, const float* __restrict__ B,
                  float* __restrict__ C, int M, int N, int K) {
    __shared__ float As[8 * 128];
    __shared__ float Bs[8 * 128];

    const int tid = threadIdx.x;
    const int tx = tid & 15, ty = tid >> 4;
    const int bm = blockIdx.y * 128, bn = blockIdx.x * 128;

    float acc[8][8];
    #pragma unroll
    for (int i = 0; i < 8; i++)
        #pragma unroll
        for (int j = 0; j < 8; j++) acc[i][j] = 0.f;

    const int arow = tid >> 1;
    const int acol = (tid & 1) * 4;

    for (int k0 = 0; k0 < K; k0 += 8) {
        float4 av = make_float4(0.f, 0.f, 0.f, 0.f);
        if (bm + arow < M)
            av = *(const float4*)&A[(size_t)(bm + arow) * K + k0 + acol];
        As[(acol + 0) * 128 + arow] = av.x;
        As[(acol + 1) * 128 + arow] = av.y;
        As[(acol + 2) * 128 + arow] = av.z;
        As[(acol + 3) * 128 + arow] = av.w;
        float4 bv = *(const float4*)&B[(size_t)(bn + arow) * K + k0 + acol];
        Bs[(acol + 0) * 128 + arow] = bv.x;
        Bs[(acol + 1) * 128 + arow] = bv.y;
        Bs[(acol + 2) * 128 + arow] = bv.z;
        Bs[(acol + 3) * 128 + arow] = bv.w;
        __syncthreads();

        #pragma unroll
        for (int kk = 0; kk < 8; kk++) {
            float a[8], b[8];
            *(float4*)&a[0] = *(const float4*)&As[kk * 128 + ty * 8];
            *(float4*)&a[4] = *(const float4*)&As[kk * 128 + ty * 8 + 4];
            *(float4*)&b[0] = *(const float4*)&Bs[kk * 128 + tx * 8];
            *(float4*)&b[4] = *(const float4*)&Bs[kk * 128 + tx * 8 + 4];
            #pragma unroll
            for (int i = 0; i < 8; i++)
                #pragma unroll
                for (int j = 0; j < 8; j++)
                    acc[i][j] = fmaf(a[i], b[j], acc[i][j]);
        }
        __syncthreads();
    }

    #pragma unroll
    for (int i = 0; i < 8; i++) {
        int row = bm + ty * 8 + i;
        if (row >= M) continue;
        #pragma unroll
        for (int j = 0; j < 8; j++)
            C[(size_t)row * N + bn + tx * 8 + j] = acc[i][j];
    }
}

// ================= HMMA flash attention v3 =================
// 256 threads (8 warps), q-tile 128 rows, kv-tile 64 rows.
// Q/K/V pre-split bf16 in global; cp.async double-buffered K/V; trans-ldmatrix PV.
#define ATSM (32768 + 2 * 32768)   // Q 32KB + 2 KV stages x 32KB

__global__ __launch_bounds__(256)
void attn_mma(const bf16* __restrict__ qh, const bf16* __restrict__ ql,
              const bf16* __restrict__ kh, const bf16* __restrict__ kl,
              const bf16* __restrict__ vh, const bf16* __restrict__ vl,
              bf16* __restrict__ oh, bf16* __restrict__ ol) {
    extern __shared__ char smn[];
    const uint32_t uq = smem_u32(smn);   // q_h @0, q_l @16384; stage s @32768+s*32768

    const int tid = threadIdx.x;
    const int lane = tid & 31, w = tid >> 5;
    const int qi = blockIdx.x;
    const int b = blockIdx.y / NHEAD, h = blockIdx.y % NHEAD;
    const int lr = ((lane >> 3) & 1) * 8 + (lane & 7);
    const int lk = lane >> 4;
    const int g = lane >> 2, tq = lane & 3;
    const int gi = lane >> 3;
    const int pv_row = ((gi >> 1) & 1) * 8 + (lane & 7);
    const int pv_col = (gi & 1) * 8;

    // ---- Q tile: 128 rows x 128B (hi+lo), cp.async ----
    #pragma unroll
    for (int it = 0; it < 4; it++) {
        int i = tid + it * 256;
        int row = i >> 3, seg = i & 7;
        uint32_t off = SWZ(row * 128 + seg * 16);
        size_t gq = (size_t)(b * TT + qi * 128 + row) * DM + h * HDIM + seg * 8;
        CP16(uq + off,         qh + gq);
        CP16(uq + 16384 + off, ql + gq);
    }
    CP_COMMIT();   // group: Q

    const int nkt = 2 * (qi + 1);
    auto load_kv = [&](int kt, int sb) {
        uint32_t st = uq + 32768 + sb * 32768;
        #pragma unroll
        for (int it = 0; it < 8; it++) {
            int i = tid + it * 256;
            int bufid = i >> 9;          // 0:kh 1:kl 2:vh 3:vl
            int j = i & 511;
            int row = j >> 3, seg = j & 7;
            uint32_t off = bufid * 8192 + SWZ(row * 128 + seg * 16);
            size_t gg = (size_t)(b * TT + kt * 64 + row) * DM + h * HDIM + seg * 8;
            const bf16* src = (bufid == 0) ? kh : (bufid == 1) ? kl : (bufid == 2) ? vh : vl;
            CP16(st + off, src + gg);
        }
    };

    load_kv(0, 0); CP_COMMIT();   // group: kv0

    CP_WAIT1();                   // Q done (kv0 may be in flight)
    __syncthreads();

    uint32_t qAh[4][4], qAl[4][4];
    #pragma unroll
    for (int kk = 0; kk < 4; kk++) {
        uint32_t off = SWZ((w * 16 + lr) * 128 + (kk * 2 + lk) * 16);
        LDM4(qAh[kk][0], qAh[kk][1], qAh[kk][2], qAh[kk][3], uq + off);
        LDM4(qAl[kk][0], qAl[kk][1], qAl[kk][2], qAl[kk][3], uq + 16384 + off);
    }

    float m0 = -1e30f, m1 = -1e30f, l0 = 0.f, l1 = 0.f;
    float o[8][4];
    #pragma unroll
    for (int j = 0; j < 8; j++)
        #pragma unroll
        for (int q = 0; q < 4; q++) o[j][q] = 0.f;

    const int rg0  = qi * 128 + w * 16 + g;
    const int wmax = qi * 128 + w * 16 + 15;

    for (int kt = 0; kt < nkt; kt++) {
        if (kt + 1 < nkt) { load_kv(kt + 1, (kt + 1) & 1); CP_COMMIT(); CP_WAIT1(); }
        else              { CP_WAIT0(); }
        __syncthreads();

        if (kt * 64 <= wmax) {   // tile has unmasked columns for this warp
            uint32_t st  = uq + 32768 + (kt & 1) * 32768;
            uint32_t ukh = st, ukl = st + 8192, uvh = st + 16384, uvl = st + 24576;

            // ---- S = Q @ K^T ----
            float s[8][4];
            #pragma unroll
            for (int j = 0; j < 8; j++)
                #pragma unroll
                for (int q = 0; q < 4; q++) s[j][q] = 0.f;

            #pragma unroll
            for (int kk = 0; kk < 4; kk++) {
                uint32_t th[4][4], tl[4][4];
                #pragma unroll
                for (int nb = 0; nb < 4; nb++) {
                    uint32_t off = SWZ((nb * 16 + lr) * 128 + (kk * 2 + lk) * 16);
                    LDM4(th[nb][0], th[nb][1], th[nb][2], th[nb][3], ukh + off);
                    LDM4(tl[nb][0], tl[nb][1], tl[nb][2], tl[nb][3], ukl + off);
                }
                #pragma unroll
                for (int nb = 0; nb < 4; nb++) {
                    uint32_t B0h[2] = {th[nb][0], th[nb][2]};
                    uint32_t B1h[2] = {th[nb][1], th[nb][3]};
                    uint32_t B0l[2] = {tl[nb][0], tl[nb][2]};
                    uint32_t B1l[2] = {tl[nb][1], tl[nb][3]};
                    MMA(s[2*nb],   qAh[kk], B0h);
                    MMA(s[2*nb],   qAh[kk], B0l);
                    MMA(s[2*nb],   qAl[kk], B0h);
                    MMA(s[2*nb+1], qAh[kk], B1h);
                    MMA(s[2*nb+1], qAh[kk], B1l);
                    MMA(s[2*nb+1], qAl[kk], B1h);
                }
            }

            #pragma unroll
            for (int j = 0; j < 8; j++) {
                s[j][0] *= 0.125f; s[j][1] *= 0.125f; s[j][2] *= 0.125f; s[j][3] *= 0.125f;
            }
            if (kt >= nkt - 2) {
                #pragma unroll
                for (int j = 0; j < 8; j++) {
                    int col = kt * 64 + j * 8 + tq * 2;
                    if (col     > rg0)     s[j][0] = -1e30f;
                    if (col + 1 > rg0)     s[j][1] = -1e30f;
                    if (col     > rg0 + 8) s[j][2] = -1e30f;
                    if (col + 1 > rg0 + 8) s[j][3] = -1e30f;
                }
            }

            float mt0 = -1e30f, mt1 = -1e30f;
            #pragma unroll
            for (int j = 0; j < 8; j++) {
                mt0 = fmaxf(mt0, fmaxf(s[j][0], s[j][1]));
                mt1 = fmaxf(mt1, fmaxf(s[j][2], s[j][3]));
            }
            mt0 = fmaxf(mt0, __shfl_xor_sync(0xffffffffu, mt0, 1));
            mt0 = fmaxf(mt0, __shfl_xor_sync(0xffffffffu, mt0, 2));
            mt1 = fmaxf(mt1, __shfl_xor_sync(0xffffffffu, mt1, 1));
            mt1 = fmaxf(mt1, __shfl_xor_sync(0xffffffffu, mt1, 2));
            float mn0 = fmaxf(m0, mt0), mn1 = fmaxf(m1, mt1);
            float a0 = __expf(m0 - mn0), a1 = __expf(m1 - mn1);
            m0 = mn0; m1 = mn1;

            float sum0 = 0.f, sum1 = 0.f;
            #pragma unroll
            for (int j = 0; j < 8; j++) {
                s[j][0] = __expf(s[j][0] - mn0);
                s[j][1] = __expf(s[j][1] - mn0);
                s[j][2] = __expf(s[j][2] - mn1);
                s[j][3] = __expf(s[j][3] - mn1);
                sum0 += s[j][0] + s[j][1];
                sum1 += s[j][2] + s[j][3];
            }
            sum0 += __shfl_xor_sync(0xffffffffu, sum0, 1);
            sum0 += __shfl_xor_sync(0xffffffffu, sum0, 2);
            sum1 += __shfl_xor_sync(0xffffffffu, sum1, 1);
            sum1 += __shfl_xor_sync(0xffffffffu, sum1, 2);
            l0 = l0 * a0 + sum0;
            l1 = l1 * a1 + sum1;
            #pragma unroll
            for (int j = 0; j < 8; j++) {
                o[j][0] *= a0; o[j][1] *= a0; o[j][2] *= a1; o[j][3] *= a1;
            }

            uint32_t pH[4][4], pL[4][4];
            #pragma unroll
            for (int kk = 0; kk < 4; kk++) {
                splitpack(s[2*kk][0],   s[2*kk][1],   pH[kk][0], pL[kk][0]);
                splitpack(s[2*kk][2],   s[2*kk][3],   pH[kk][1], pL[kk][1]);
                splitpack(s[2*kk+1][0], s[2*kk+1][1], pH[kk][2], pL[kk][2]);
                splitpack(s[2*kk+1][2], s[2*kk+1][3], pH[kk][3], pL[kk][3]);
            }

            // ---- O += P @ V (trans ldmatrix; V row-major) ----
            #pragma unroll
            for (int kk = 0; kk < 4; kk++) {
                uint32_t th[4][4], tl[4][4];
                #pragma unroll
                for (int nb = 0; nb < 4; nb++) {
                    uint32_t off = SWZ((kk * 16 + pv_row) * 128 + (nb * 16 + pv_col) * 2);
                    LDM4T(th[nb][0], th[nb][1], th[nb][2], th[nb][3], uvh + off);
                    LDM4T(tl[nb][0], tl[nb][1], tl[nb][2], tl[nb][3], uvl + off);
                }
                #pragma unroll
                for (int nb = 0; nb < 4; nb++) {
                    uint32_t B0h[2] = {th[nb][0], th[nb][2]};
                    uint32_t B1h[2] = {th[nb][1], th[nb][3]};
                    uint32_t B0l[2] = {tl[nb][0], tl[nb][2]};
                    uint32_t B1l[2] = {tl[nb][1], tl[nb][3]};
                    MMA(o[2*nb],   pH[kk], B0h);
                    MMA(o[2*nb],   pH[kk], B0l);
                    MMA(o[2*nb],   pL[kk], B0h);
                    MMA(o[2*nb+1], pH[kk], B1h);
                    MMA(o[2*nb+1], pH[kk], B1l);
                    MMA(o[2*nb+1], pL[kk], B1h);
                }
            }
        }
        __syncthreads();
    }

    float i0 = 1.f / l0, i1 = 1.f / l1;
    size_t r0 = (size_t)(b * TT + qi * 128 + w * 16 + g);
    #pragma unroll
    for (int j = 0; j < 8; j++) {
        int col = h * HDIM + j * 8 + tq * 2;
        split2_store(oh, ol, r0 * DM + col,       o[j][0] * i0, o[j][1] * i0);
        split2_store(oh, ol, (r0 + 8) * DM + col, o[j][2] * i1, o[j][3] * i1);
    }
}

// ---------------- launcher ----------------
extern "C" void kernel_launch(void* const* d_in, const int* in_sizes, int n_in,
                              void* d_out, int out_size) {
    const int*   idx    = (const int*)  d_in[0];
    const float* wte    = (const float*)d_in[1];
    const float* wpe    = (const float*)d_in[2];
    const float* ln1_w  = (const float*)d_in[3];
    const float* ln1_b  = (const float*)d_in[4];
    const float* caw    = (const float*)d_in[5];
    const float* cab    = (const float*)d_in[6];
    const float* cpw    = (const float*)d_in[7];
    const float* cpb    = (const float*)d_in[8];
    const float* ln2_w  = (const float*)d_in[9];
    const float* ln2_b  = (const float*)d_in[10];
    const float* cfw    = (const float*)d_in[11];
    const float* cfb    = (const float*)d_in[12];
    const float* swW    = (const float*)d_in[13];
    const float* swV    = (const float*)d_in[14];
    const float* swb    = (const float*)d_in[15];
    const float* swc    = (const float*)d_in[16];
    const float* mpw    = (const float*)d_in[17];
    const float* mpb    = (const float*)d_in[18];
    const float* lnf_w  = (const float*)d_in[19];
    const float* lnf_b  = (const float*)d_in[20];
    const float* lmw    = (const float*)d_in[21];
    float* out = (float*)d_out;

    float *x, *a, *xf;
    bf16 *xn_h, *xn_l, *att_h, *att_l, *h_h, *h_l, *c2_h, *c2_l;
    bf16 *q_h, *q_l, *k_h, *k_l, *v_h, *v_l;
    bf16 *wq_h, *wq_l, *wp_h, *wp_l, *wf_h, *wf_l, *wW_h, *wW_l, *wV_h, *wV_l, *wm_h, *wm_l;
    cudaGetSymbolAddress((void**)&x,    g_x);
    cudaGetSymbolAddress((void**)&a,    g_a);
    cudaGetSymbolAddress((void**)&xf,   g_xf);
    cudaGetSymbolAddress((void**)&xn_h, g_xn_h);  cudaGetSymbolAddress((void**)&xn_l, g_xn_l);
    cudaGetSymbolAddress((void**)&att_h,g_att_h); cudaGetSymbolAddress((void**)&att_l,g_att_l);
    cudaGetSymbolAddress((void**)&h_h,  g_h_h);   cudaGetSymbolAddress((void**)&h_l,  g_h_l);
    cudaGetSymbolAddress((void**)&c2_h, g_c2_h);  cudaGetSymbolAddress((void**)&c2_l, g_c2_l);
    cudaGetSymbolAddress((void**)&q_h,  g_q_h);   cudaGetSymbolAddress((void**)&q_l,  g_q_l);
    cudaGetSymbolAddress((void**)&k_h,  g_k_h);   cudaGetSymbolAddress((void**)&k_l,  g_k_l);
    cudaGetSymbolAddress((void**)&v_h,  g_v_h);   cudaGetSymbolAddress((void**)&v_l,  g_v_l);
    cudaGetSymbolAddress((void**)&wq_h, g_wq_h);  cudaGetSymbolAddress((void**)&wq_l, g_wq_l);
    cudaGetSymbolAddress((void**)&wp_h, g_wp_h);  cudaGetSymbolAddress((void**)&wp_l, g_wp_l);
    cudaGetSymbolAddress((void**)&wf_h, g_wf_h);  cudaGetSymbolAddress((void**)&wf_l, g_wf_l);
    cudaGetSymbolAddress((void**)&wW_h, g_wW_h);  cudaGetSymbolAddress((void**)&wW_l, g_wW_l);
    cudaGetSymbolAddress((void**)&wV_h, g_wV_h);  cudaGetSymbolAddress((void**)&wV_l, g_wV_l);
    cudaGetSymbolAddress((void**)&wm_h, g_wm_h);  cudaGetSymbolAddress((void**)&wm_l, g_wm_l);

    cudaFuncSetAttribute(attn_mma, cudaFuncAttributeMaxDynamicSharedMemorySize, ATSM);
    cudaFuncSetAttribute(gemm_mma<GM_F32>,    cudaFuncAttributeMaxDynamicSharedMemorySize, GSMEM);
    cudaFuncSetAttribute(gemm_mma<GM_RES>,    cudaFuncAttributeMaxDynamicSharedMemorySize, GSMEM);
    cudaFuncSetAttribute(gemm_mma<GM_SPLIT>,  cudaFuncAttributeMaxDynamicSharedMemorySize, GSMEM);
    cudaFuncSetAttribute(gemm_mma<GM_SWIGLU>, cudaFuncAttributeMaxDynamicSharedMemorySize, GSMEM);
    cudaFuncSetAttribute(gemm_mma<GM_QKV>,    cudaFuncAttributeMaxDynamicSharedMemorySize, GSMEM);

    split_all<<<dim3(9216, 4), 256>>>(
        caw, wq_h, wq_l, NL * D3 * DM / 4,
        cpw, wp_h, wp_l, NL * DM * DM / 4,
        cfw, wf_h, wf_l, NL * D4 * DM / 4,
        mpw, wm_h, wm_l, NL * DM * D4 / 4);

    embed_kernel<<<BT, 192>>>(idx, wte, wpe, x);

    for (int l = 0; l < NL; l++) {
        size_t oq = (size_t)l * D3 * DM, op = (size_t)l * DM * DM;
        size_t of = (size_t)l * D4 * DM, ow = (size_t)l * D4 * D4, om = (size_t)l * DM * D4;
        ln_kernel<true><<<BT, 256>>>(x, DM, ln1_w + l * DM, ln1_b + l * DM, nullptr, xn_h, xn_l);
        gemm_mma<GM_QKV><<<dim3(D3 / 128, BT / 128), 256, GSMEM>>>(
            xn_h, xn_l, wq_h + oq, wq_l + oq, cab + l * D3, nullptr,
            nullptr, nullptr, nullptr, D3, DM);
        attn_mma<<<dim3(TT / 128, BB * NHEAD), 256, ATSM>>>(
            q_h, q_l, k_h, k_l, v_h, v_l, att_h, att_l);
        gemm_mma<GM_RES><<<dim3(DM / 128, BT / 128), 256, GSMEM>>>(
            att_h, att_l, wp_h + op, wp_l + op, cpb + l * DM, nullptr, x, nullptr, nullptr, DM, DM);
        ln_kernel<true><<<BT, 256>>>(x, DM, ln2_w + l * DM, ln2_b + l * DM, nullptr, xn_h, xn_l);
        if (l == 0) {
            transpose_all<<<dim3(D4 / 32, D4 / 32, 2 * NL), dim3(32, 8)>>>(
                swW, swV, wW_h, wW_l, wV_h, wV_l);
        }
        gemm_mma<GM_SPLIT><<<dim3(D4 / 128, BT / 128), 256, GSMEM>>>(
            xn_h, xn_l, wf_h + of, wf_l + of, cfb + l * D4, nullptr, nullptr, h_h, h_l, D4, DM);
        gemm_mma<GM_F32><<<dim3(D4 / 128, BT / 128), 256, GSMEM>>>(
            h_h, h_l, wW_h + ow, wW_l + ow, swb + l * D4, nullptr, a, nullptr, nullptr, D4, D4);
        gemm_mma<GM_SWIGLU><<<dim3(D4 / 128, BT / 128), 256, GSMEM>>>(
            h_h, h_l, wV_h + ow, wV_l + ow, swc + l * D4, a, nullptr, c2_h, c2_l, D4, D4);
        gemm_mma<GM_RES><<<dim3(DM / 128, BT / 128), 256, GSMEM>>>(
            c2_h, c2_l, wm_h + om, wm_l + om, mpb + l * DM, nullptr, x, nullptr, nullptr, DM, D4);
    }

    ln_kernel<false><<<BB, 256>>>(x + (size_t)(TT - 1) * DM, (size_t)TT * DM,
                                  lnf_w, lnf_b, xf, nullptr, nullptr);
    sgemm_kernel<<<dim3(VV / 128, 1), 256>>>(xf, lmw, out, BB, VV, DM);
}

// round 13
// speedup vs baseline: 1.0442x; 1.0442x over previous
#include <cuda_runtime.h>
#include <cuda_bf16.h>
#include <math.h>
#include <stdint.h>

#define BB 4
#define TT 1024
#define DM 768
#define NHEAD 12
#define HDIM 64
#define NL 4
#define VV 50304
#define D3 2304
#define D4 3072
#define BT 4096   // B*T

typedef __nv_bfloat16 bf16;

// ---------------- scratch (device globals; no allocation anywhere) ----------------
__device__ float g_x  [BT * DM];
__device__ float g_qkv[BT * D3];
__device__ float g_a  [BT * D4];
__device__ float g_xf [BB * DM];
__device__ float g_part[2 * BT * DM];     // split-K partials for mlp_proj
__device__ bf16 g_xn_h [BT * DM],  g_xn_l [BT * DM];
__device__ bf16 g_att_h[BT * DM],  g_att_l[BT * DM];
__device__ bf16 g_h_h  [BT * D4],  g_h_l  [BT * D4];
__device__ bf16 g_c2_h [BT * D4],  g_c2_l [BT * D4];
// split-bf16 weights, all stored [N][K] (K contiguous)
__device__ bf16 g_wq_h[NL * D3 * DM], g_wq_l[NL * D3 * DM];
__device__ bf16 g_wp_h[NL * DM * DM], g_wp_l[NL * DM * DM];
__device__ bf16 g_wf_h[NL * D4 * DM], g_wf_l[NL * D4 * DM];
__device__ bf16 g_wW_h[NL * D4 * D4], g_wW_l[NL * D4 * D4];
__device__ bf16 g_wV_h[NL * D4 * D4], g_wV_l[NL * D4 * D4];
__device__ bf16 g_wm_h[NL * DM * D4], g_wm_l[NL * DM * D4];

// ================= asm helpers (base sm_103 features only) =================
__device__ __forceinline__ uint32_t smem_u32(const void* p) {
    uint32_t a;
    asm("{ .reg .u64 t; cvta.to.shared.u64 t, %1; cvt.u32.u64 %0, t; }" : "=r"(a) : "l"(p));
    return a;
}
__device__ __forceinline__ float fexp2(float x) {
    float r;
    asm("ex2.approx.ftz.f32 %0, %1;" : "=f"(r) : "f"(x));
    return r;
}
#define SWZ(off) ((off) ^ (((off) >> 3) & 0x70))

#define CP16(dst, src) \
    asm volatile("cp.async.cg.shared.global [%0], [%1], 16;" :: "r"(dst), "l"(src) : "memory")
#define CP_COMMIT() asm volatile("cp.async.commit_group;" ::: "memory")
#define CP_WAIT1()  asm volatile("cp.async.wait_group 1;"  ::: "memory")

#define LDM4(r0, r1, r2, r3, addr) \
    asm volatile("ldmatrix.sync.aligned.m8n8.x4.shared.b16 {%0,%1,%2,%3}, [%4];" \
                 : "=r"(r0), "=r"(r1), "=r"(r2), "=r"(r3) : "r"(addr))

#define LDM4T(r0, r1, r2, r3, addr) \
    asm volatile("ldmatrix.sync.aligned.m8n8.x4.trans.shared.b16 {%0,%1,%2,%3}, [%4];" \
                 : "=r"(r0), "=r"(r1), "=r"(r2), "=r"(r3) : "r"(addr))

#define MMA(D, A, B) \
    asm volatile("mma.sync.aligned.m16n8k16.row.col.f32.bf16.bf16.f32 " \
                 "{%0,%1,%2,%3}, {%4,%5,%6,%7}, {%8,%9}, {%0,%1,%2,%3};" \
                 : "+f"((D)[0]), "+f"((D)[1]), "+f"((D)[2]), "+f"((D)[3]) \
                 : "r"((A)[0]), "r"((A)[1]), "r"((A)[2]), "r"((A)[3]), \
                   "r"((B)[0]), "r"((B)[1]))

__device__ __forceinline__ void split2_store(bf16* H, bf16* L, size_t off, float v0, float v1) {
    bf16 h0 = __float2bfloat16(v0), h1 = __float2bfloat16(v1);
    bf16 l0 = __float2bfloat16(v0 - __bfloat162float(h0));
    bf16 l1 = __float2bfloat16(v1 - __bfloat162float(h1));
    *(__nv_bfloat162*)(H + off) = __halves2bfloat162(h0, h1);
    *(__nv_bfloat162*)(L + off) = __halves2bfloat162(l0, l1);
}

__device__ __forceinline__ void split4(float4 v, uint2& hp, uint2& lp) {
    bf16 a = __float2bfloat16(v.x), b = __float2bfloat16(v.y);
    bf16 c = __float2bfloat16(v.z), d = __float2bfloat16(v.w);
    bf16 e = __float2bfloat16(v.x - __bfloat162float(a));
    bf16 f = __float2bfloat16(v.y - __bfloat162float(b));
    bf16 g = __float2bfloat16(v.z - __bfloat162float(c));
    bf16 k = __float2bfloat16(v.w - __bfloat162float(d));
    hp.x = (uint32_t)__bfloat16_as_ushort(a) | ((uint32_t)__bfloat16_as_ushort(b) << 16);
    hp.y = (uint32_t)__bfloat16_as_ushort(c) | ((uint32_t)__bfloat16_as_ushort(d) << 16);
    lp.x = (uint32_t)__bfloat16_as_ushort(e) | ((uint32_t)__bfloat16_as_ushort(f) << 16);
    lp.y = (uint32_t)__bfloat16_as_ushort(g) | ((uint32_t)__bfloat16_as_ushort(k) << 16);
}

__device__ __forceinline__ void splitpack(float x, float y, uint32_t& hi, uint32_t& lo) {
    bf16 xh = __float2bfloat16(x), yh = __float2bfloat16(y);
    bf16 xl = __float2bfloat16(x - __bfloat162float(xh));
    bf16 yl = __float2bfloat16(y - __bfloat162float(yh));
    hi = (uint32_t)__bfloat16_as_ushort(xh) | ((uint32_t)__bfloat16_as_ushort(yh) << 16);
    lo = (uint32_t)__bfloat16_as_ushort(xl) | ((uint32_t)__bfloat16_as_ushort(yl) << 16);
}

// ---------------- weight conversion ----------------
__global__ void split_all(const float* __restrict__ s0, bf16* h0, bf16* l0, int n0,
                          const float* __restrict__ s1, bf16* h1, bf16* l1, int n1,
                          const float* __restrict__ s2, bf16* h2, bf16* l2, int n2,
                          const float* __restrict__ s3, bf16* h3, bf16* l3, int n3) {
    const float* s; bf16 *h, *l; int n;
    switch (blockIdx.y) {
        case 0: s = s0; h = h0; l = l0; n = n0; break;
        case 1: s = s1; h = h1; l = l1; n = n1; break;
        case 2: s = s2; h = h2; l = l2; n = n2; break;
        default:s = s3; h = h3; l = l3; n = n3; break;
    }
    int i = blockIdx.x * blockDim.x + threadIdx.x;
    if (i >= n) return;
    float4 v = ((const float4*)s)[i];
    split2_store(h, l, (size_t)i * 4,     v.x, v.y);
    split2_store(h, l, (size_t)i * 4 + 2, v.z, v.w);
}

__global__ void transpose_all(const float* __restrict__ W, const float* __restrict__ V,
                              bf16* __restrict__ Wh, bf16* __restrict__ Wl,
                              bf16* __restrict__ Vh, bf16* __restrict__ Vl) {
    __shared__ float t[32][33];
    int z = blockIdx.z;
    int l = (z < NL) ? z : z - NL;
    const float* s = ((z < NL) ? W : V) + (size_t)l * D4 * D4;
    bf16* H = ((z < NL) ? Wh : Vh) + (size_t)l * D4 * D4;
    bf16* L = ((z < NL) ? Wl : Vl) + (size_t)l * D4 * D4;
    int n0 = blockIdx.x * 32, k0 = blockIdx.y * 32;
    int cx = threadIdx.x;
    #pragma unroll
    for (int r = threadIdx.y; r < 32; r += 8)
        t[r][cx] = s[(size_t)(k0 + r) * D4 + n0 + cx];
    __syncthreads();
    #pragma unroll
    for (int r = threadIdx.y; r < 32; r += 8) {
        float v = t[cx][r];
        size_t off = (size_t)(n0 + r) * D4 + k0 + cx;
        bf16 h = __float2bfloat16(v);
        H[off] = h;
        L[off] = __float2bfloat16(v - __bfloat162float(h));
    }
}

// ---------------- embedding ----------------
__global__ void embed_kernel(const int* __restrict__ idx, const float* __restrict__ wte,
                             const float* __restrict__ wpe, float* __restrict__ x) {
    int bt = blockIdx.x;
    int t  = bt & (TT - 1);
    int tok = idx[bt];
    int c = threadIdx.x * 4;
    float4 a = *(const float4*)&wte[(size_t)tok * DM + c];
    float4 p = *(const float4*)&wpe[(size_t)t   * DM + c];
    a.x += p.x; a.y += p.y; a.z += p.z; a.w += p.w;
    *(float4*)&x[(size_t)bt * DM + c] = a;
}

// ---------------- split-K partial reduce: x += p0 + p1 ----------------
__global__ void addparts(float* __restrict__ x, const float* __restrict__ p, int n4) {
    int i = blockIdx.x * blockDim.x + threadIdx.x;
    if (i >= n4) return;
    float4 xv = ((const float4*)x)[i];
    float4 a = ((const float4*)p)[i];
    float4 b = ((const float4*)(p + (size_t)BT * DM))[i];
    xv.x += a.x + b.x; xv.y += a.y + b.y; xv.z += a.z + b.z; xv.w += a.w + b.w;
    ((float4*)x)[i] = xv;
}

// ---------------- layernorm ----------------
template <bool SPLIT>
__global__ __launch_bounds__(256)
void ln_kernel(const float* __restrict__ x, size_t rstride,
               const float* __restrict__ w, const float* __restrict__ b,
               float* __restrict__ yf, bf16* __restrict__ yh, bf16* __restrict__ yl) {
    const float* xr = x + (size_t)blockIdx.x * rstride;
    int tid = threadIdx.x;

    float v0 = xr[tid], v1 = xr[tid + 256], v2 = xr[tid + 512];
    float s  = v0 + v1 + v2;
    float s2 = v0 * v0 + v1 * v1 + v2 * v2;
    #pragma unroll
    for (int off = 16; off; off >>= 1) {
        s  += __shfl_xor_sync(0xffffffffu, s,  off);
        s2 += __shfl_xor_sync(0xffffffffu, s2, off);
    }
    __shared__ float sh_s[8], sh_s2[8];
    int wid = tid >> 5, lane = tid & 31;
    if (lane == 0) { sh_s[wid] = s; sh_s2[wid] = s2; }
    __syncthreads();
    float tot = 0.f, tot2 = 0.f;
    #pragma unroll
    for (int i = 0; i < 8; i++) { tot += sh_s[i]; tot2 += sh_s2[i]; }
    const float inv = 1.0f / (float)DM;
    float mean = tot * inv;
    float var  = tot2 * inv - mean * mean;
    float rstd = rsqrtf(var + 1e-5f);

    size_t base = (size_t)blockIdx.x * DM;
    float o0 = (v0 - mean) * rstd * w[tid]       + b[tid];
    float o1 = (v1 - mean) * rstd * w[tid + 256] + b[tid + 256];
    float o2 = (v2 - mean) * rstd * w[tid + 512] + b[tid + 512];
    if (SPLIT) {
        bf16 h0 = __float2bfloat16(o0);
        yh[base + tid] = h0;       yl[base + tid]       = __float2bfloat16(o0 - __bfloat162float(h0));
        bf16 h1 = __float2bfloat16(o1);
        yh[base + tid + 256] = h1; yl[base + tid + 256] = __float2bfloat16(o1 - __bfloat162float(h1));
        bf16 h2 = __float2bfloat16(o2);
        yh[base + tid + 512] = h2; yl[base + tid + 512] = __float2bfloat16(o2 - __bfloat162float(h2));
    } else {
        yf[base + tid]       = o0;
        yf[base + tid + 256] = o1;
        yf[base + tid + 512] = o2;
    }
}

// ================= mma.sync split-bf16 GEMM (R8 loop; lda + split-K support) ======
#define GM_F32    0
#define GM_RES    1
#define GM_SPLIT  2
#define GM_SWIGLU 3
#define GM_PART   4   // write partial (+bias on z==0) to Cf + z*BT*DM

#define GSTAGE 65536
#define GSMEM  (3 * GSTAGE + 1024)

struct Frags {
    uint32_t aH[2][4], aL[2][4], bH[8][2], bL[8][2];
};

template <int MODE>
__global__ __launch_bounds__(256, 1)
void gemm_mma(const bf16* __restrict__ Ah, const bf16* __restrict__ Al,
              const bf16* __restrict__ Bh, const bf16* __restrict__ Bl,
              const float* __restrict__ bias, const float* __restrict__ aux,
              float* __restrict__ Cf, bf16* __restrict__ Ch, bf16* __restrict__ Cl,
              int N, int K, int lda) {
    extern __shared__ char dyn[];
    uint32_t base = (smem_u32(dyn) + 1023) & ~1023u;

    const int tid = threadIdx.x;
    const int bm = blockIdx.y * 128, bn = blockIdx.x * 128;
    const int koff = blockIdx.z * K;
    const int lane = tid & 31, wid = tid >> 5;
    const int wm = wid & 3, wn = wid >> 2;

    const int lr = ((lane >> 3) & 1) * 8 + (lane & 7);
    const int lk = lane >> 4;

    float d[2][8][4];
    #pragma unroll
    for (int i = 0; i < 2; i++)
        #pragma unroll
        for (int j = 0; j < 8; j++)
            #pragma unroll
            for (int q = 0; q < 4; q++) d[i][j][q] = 0.f;

    const int nkt = K >> 6;

    auto load_stage = [&](int kt, int sb) {
        uint32_t st = base + sb * GSTAGE;
        int k0 = koff + (kt << 6);
        #pragma unroll
        for (int i = 0; i < 4; i++) {
            int row = (tid >> 3) + i * 32;
            int seg = tid & 7;
            uint32_t soff = SWZ(row * 128 + seg * 16);
            size_t ga = (size_t)(bm + row) * lda + k0 + seg * 8;
            size_t gb = (size_t)(bn + row) * lda + k0 + seg * 8;
            CP16(st + soff,         Ah + ga);
            CP16(st + 16384 + soff, Al + ga);
            CP16(st + 32768 + soff, Bh + gb);
            CP16(st + 49152 + soff, Bl + gb);
        }
    };

    auto load_frags = [&](uint32_t st, int ks, Frags& f) {
        #pragma unroll
        for (int am = 0; am < 2; am++) {
            int row = wm * 32 + am * 16 + lr;
            uint32_t off = SWZ(row * 128 + (ks * 2 + lk) * 16);
            LDM4(f.aH[am][0], f.aH[am][1], f.aH[am][2], f.aH[am][3], st + off);
            LDM4(f.aL[am][0], f.aL[am][1], f.aL[am][2], f.aL[am][3], st + 16384 + off);
        }
        #pragma unroll
        for (int nb = 0; nb < 4; nb++) {
            int row = wn * 64 + nb * 16 + lr;
            uint32_t off = SWZ(row * 128 + (ks * 2 + lk) * 16);
            uint32_t t0, t1, t2, t3;
            LDM4(t0, t1, t2, t3, st + 32768 + off);
            f.bH[2*nb][0] = t0; f.bH[2*nb][1] = t2; f.bH[2*nb+1][0] = t1; f.bH[2*nb+1][1] = t3;
            LDM4(t0, t1, t2, t3, st + 49152 + off);
            f.bL[2*nb][0] = t0; f.bL[2*nb][1] = t2; f.bL[2*nb+1][0] = t1; f.bL[2*nb+1][1] = t3;
        }
    };
    auto do_mma = [&](Frags& f) {
        #pragma unroll
        for (int am = 0; am < 2; am++)
            #pragma unroll
            for (int an = 0; an < 8; an++) {
                MMA(d[am][an], f.aH[am], f.bH[an]);
                MMA(d[am][an], f.aH[am], f.bL[an]);
                MMA(d[am][an], f.aL[am], f.bH[an]);
            }
    };

    load_stage(0, 0); CP_COMMIT();
    load_stage(1, 1); CP_COMMIT();

    Frags fr[2];
    for (int kt = 0; kt < nkt; kt++) {
        CP_WAIT1();
        __syncthreads();
        if (kt + 2 < nkt) load_stage(kt + 2, (kt + 2) % 3);
        CP_COMMIT();

        uint32_t st = base + (kt % 3) * GSTAGE;
        load_frags(st, 0, fr[0]);
        #pragma unroll
        for (int ks = 0; ks < 4; ks++) {
            if (ks < 3) load_frags(st, ks + 1, fr[(ks + 1) & 1]);
            do_mma(fr[ks & 1]);
        }
    }

    const int g = lane >> 2, tq = lane & 3;
    #pragma unroll
    for (int am = 0; am < 2; am++)
        #pragma unroll
        for (int an = 0; an < 8; an++) {
            int r0 = bm + wm * 32 + am * 16 + g;
            int c  = bn + wn * 64 + an * 8 + tq * 2;
            #pragma unroll
            for (int half = 0; half < 2; half++) {
                int row = r0 + half * 8;
                float v0 = d[am][an][half * 2];
                float v1 = d[am][an][half * 2 + 1];
                if (MODE != GM_PART || blockIdx.z == 0) { v0 += bias[c]; v1 += bias[c + 1]; }
                size_t off = (size_t)row * N + c;
                if (MODE == GM_F32) {
                    *(float2*)(Cf + off) = make_float2(v0, v1);
                } else if (MODE == GM_RES) {
                    float2 o = *(const float2*)(Cf + off);
                    *(float2*)(Cf + off) = make_float2(v0 + o.x, v1 + o.y);
                } else if (MODE == GM_SPLIT) {
                    split2_store(Ch, Cl, off, v0, v1);
                } else if (MODE == GM_SWIGLU) {
                    float2 gg = *(const float2*)(aux + off);
                    float s0 = gg.x / (1.f + __expf(-gg.x));
                    float s1 = gg.y / (1.f + __expf(-gg.y));
                    split2_store(Ch, Cl, off, s0 * v0, s1 * v1);
                } else {  // GM_PART
                    *(float2*)(Cf + (size_t)blockIdx.z * BT * DM + off) = make_float2(v0, v1);
                }
            }
        }
}

// ---------------- SIMT sgemm (lm_head only, M=4) ----------------
__global__ __launch_bounds__(256)
void sgemm_kernel(const float* __restrict__ A, const float* __restrict__ B,
                  float* __restrict__ C, int M, int N, int K) {
    __shared__ float As[8 * 128];
    __shared__ float Bs[8 * 128];

    const int tid = threadIdx.x;
    const int tx = tid & 15, ty = tid >> 4;
    const int bm = blockIdx.y * 128, bn = blockIdx.x * 128;

    float acc[8][8];
    #pragma unroll
    for (int i = 0; i < 8; i++)
        #pragma unroll
        for (int j = 0; j < 8; j++) acc[i][j] = 0.f;

    const int arow = tid >> 1;
    const int acol = (tid & 1) * 4;

    for (int k0 = 0; k0 < K; k0 += 8) {
        float4 av = make_float4(0.f, 0.f, 0.f, 0.f);
        if (bm + arow < M)
            av = *(const float4*)&A[(size_t)(bm + arow) * K + k0 + acol];
        As[(acol + 0) * 128 + arow] = av.x;
        As[(acol + 1) * 128 + arow] = av.y;
        As[(acol + 2) * 128 + arow] = av.z;
        As[(acol + 3) * 128 + arow] = av.w;
        float4 bv = *(const float4*)&B[(size_t)(bn + arow) * K + k0 + acol];
        Bs[(acol + 0) * 128 + arow] = bv.x;
        Bs[(acol + 1) * 128 + arow] = bv.y;
        Bs[(acol + 2) * 128 + arow] = bv.z;
        Bs[(acol + 3) * 128 + arow] = bv.w;
        __syncthreads();

        #pragma unroll
        for (int kk = 0; kk < 8; kk++) {
            float a[8], b[8];
            *(float4*)&a[0] = *(const float4*)&As[kk * 128 + ty * 8];
            *(float4*)&a[4] = *(const float4*)&As[kk * 128 + ty * 8 + 4];
            *(float4*)&b[0] = *(const float4*)&Bs[kk * 128 + tx * 8];
            *(float4*)&b[4] = *(const float4*)&Bs[kk * 128 + tx * 8 + 4];
            #pragma unroll
            for (int i = 0; i < 8; i++)
                #pragma unroll
                for (int j = 0; j < 8; j++)
                    acc[i][j] = fmaf(a[i], b[j], acc[i][j]);
        }
        __syncthreads();
    }

    #pragma unroll
    for (int i = 0; i < 8; i++) {
        int row = bm + ty * 8 + i;
        if (row >= M) continue;
        #pragma unroll
        for (int j = 0; j < 8; j++)
            C[(size_t)row * N + bn + tx * 8 + j] = acc[i][j];
    }
}

// ================= HMMA flash attention (split-bf16, causal, HD=64) =================
// R11 version + exp2-folded softmax (scale includes log2e; ex2.approx directly).
#define ATSM (6 * 8192)

__global__ __launch_bounds__(128)
void attn_mma(const float* __restrict__ qkv, bf16* __restrict__ oh, bf16* __restrict__ ol) {
    extern __shared__ char smn[];
    char* sq_h = smn;            char* sq_l = smn + 8192;
    char* sk_h = smn + 16384;    char* sk_l = smn + 24576;
    char* sv_h = smn + 32768;    char* sv_l = smn + 40960;
    const uint32_t uq_h = smem_u32(smn);
    const uint32_t uq_l = uq_h + 8192;
    const uint32_t uk_h = uq_h + 16384, uk_l = uq_h + 24576;
    const uint32_t uv_h = uq_h + 32768, uv_l = uq_h + 40960;

    const int tid = threadIdx.x;
    const int lane = tid & 31, w = tid >> 5;
    const int qi = blockIdx.x;
    const int b = blockIdx.y / NHEAD, h = blockIdx.y % NHEAD;
    const int lr = ((lane >> 3) & 1) * 8 + (lane & 7);
    const int lk = lane >> 4;
    const int g = lane >> 2, tq = lane & 3;
    const int gi = lane >> 3;
    const int pv_row = ((gi >> 1) & 1) * 8 + (lane & 7);
    const int pv_col = (gi & 1) * 8;

    const float SC = 0.18033688011112042f;   // 0.125 * log2(e)

    #pragma unroll
    for (int it = 0; it < 8; it++) {
        int i = tid + it * 128;
        int row = i >> 4, c4 = (i & 15) * 4;
        float4 v = *(const float4*)&qkv[(size_t)(b * TT + qi * 64 + row) * D3 + h * HDIM + c4];
        uint2 hp, lp; split4(v, hp, lp);
        uint32_t off = SWZ(row * 128 + c4 * 2);
        *(uint2*)(sq_h + off) = hp;
        *(uint2*)(sq_l + off) = lp;
    }
    __syncthreads();

    uint32_t qAh[4][4], qAl[4][4];
    #pragma unroll
    for (int kk = 0; kk < 4; kk++) {
        uint32_t off = SWZ((w * 16 + lr) * 128 + (kk * 2 + lk) * 16);
        LDM4(qAh[kk][0], qAh[kk][1], qAh[kk][2], qAh[kk][3], uq_h + off);
        LDM4(qAl[kk][0], qAl[kk][1], qAl[kk][2], qAl[kk][3], uq_l + off);
    }

    float m0 = -1e30f, m1 = -1e30f, l0 = 0.f, l1 = 0.f;
    float o[8][4];
    #pragma unroll
    for (int j = 0; j < 8; j++)
        #pragma unroll
        for (int q = 0; q < 4; q++) o[j][q] = 0.f;

    const int rg0 = qi * 64 + w * 16 + g;

    for (int kt = 0; kt <= qi; kt++) {
        __syncthreads();
        #pragma unroll
        for (int it = 0; it < 8; it++) {
            int i = tid + it * 128;
            int row = i >> 4, c4 = (i & 15) * 4;
            size_t gbase = (size_t)(b * TT + kt * 64 + row) * D3 + h * HDIM + c4;
            float4 kv = *(const float4*)&qkv[gbase + DM];
            float4 vv = *(const float4*)&qkv[gbase + 2 * DM];
            uint32_t off = SWZ(row * 128 + c4 * 2);
            uint2 hp, lp;
            split4(kv, hp, lp);
            *(uint2*)(sk_h + off) = hp;
            *(uint2*)(sk_l + off) = lp;
            split4(vv, hp, lp);
            *(uint2*)(sv_h + off) = hp;
            *(uint2*)(sv_l + off) = lp;
        }
        __syncthreads();

        float s[8][4];
        #pragma unroll
        for (int j = 0; j < 8; j++)
            #pragma unroll
            for (int q = 0; q < 4; q++) s[j][q] = 0.f;

        #pragma unroll
        for (int kk = 0; kk < 4; kk++) {
            uint32_t th[4][4], tl[4][4];
            #pragma unroll
            for (int nb = 0; nb < 4; nb++) {
                uint32_t off = SWZ((nb * 16 + lr) * 128 + (kk * 2 + lk) * 16);
                LDM4(th[nb][0], th[nb][1], th[nb][2], th[nb][3], uk_h + off);
                LDM4(tl[nb][0], tl[nb][1], tl[nb][2], tl[nb][3], uk_l + off);
            }
            #pragma unroll
            for (int nb = 0; nb < 4; nb++) {
                uint32_t B0h[2] = {th[nb][0], th[nb][2]};
                uint32_t B1h[2] = {th[nb][1], th[nb][3]};
                uint32_t B0l[2] = {tl[nb][0], tl[nb][2]};
                uint32_t B1l[2] = {tl[nb][1], tl[nb][3]};
                MMA(s[2*nb],   qAh[kk], B0h);
                MMA(s[2*nb],   qAh[kk], B0l);
                MMA(s[2*nb],   qAl[kk], B0h);
                MMA(s[2*nb+1], qAh[kk], B1h);
                MMA(s[2*nb+1], qAh[kk], B1l);
                MMA(s[2*nb+1], qAl[kk], B1h);
            }
        }

        #pragma unroll
        for (int j = 0; j < 8; j++) {
            s[j][0] *= SC; s[j][1] *= SC; s[j][2] *= SC; s[j][3] *= SC;
        }
        if (kt == qi) {
            #pragma unroll
            for (int j = 0; j < 8; j++) {
                int col = kt * 64 + j * 8 + tq * 2;
                if (col     > rg0)     s[j][0] = -1e30f;
                if (col + 1 > rg0)     s[j][1] = -1e30f;
                if (col     > rg0 + 8) s[j][2] = -1e30f;
                if (col + 1 > rg0 + 8) s[j][3] = -1e30f;
            }
        }

        float mt0 = -1e30f, mt1 = -1e30f;
        #pragma unroll
        for (int j = 0; j < 8; j++) {
            mt0 = fmaxf(mt0, fmaxf(s[j][0], s[j][1]));
            mt1 = fmaxf(mt1, fmaxf(s[j][2], s[j][3]));
        }
        mt0 = fmaxf(mt0, __shfl_xor_sync(0xffffffffu, mt0, 1));
        mt0 = fmaxf(mt0, __shfl_xor_sync(0xffffffffu, mt0, 2));
        mt1 = fmaxf(mt1, __shfl_xor_sync(0xffffffffu, mt1, 1));
        mt1 = fmaxf(mt1, __shfl_xor_sync(0xffffffffu, mt1, 2));
        float mn0 = fmaxf(m0, mt0), mn1 = fmaxf(m1, mt1);
        float a0 = fexp2(m0 - mn0), a1 = fexp2(m1 - mn1);
        m0 = mn0; m1 = mn1;

        float sum0 = 0.f, sum1 = 0.f;
        #pragma unroll
        for (int j = 0; j < 8; j++) {
            s[j][0] = fexp2(s[j][0] - mn0);
            s[j][1] = fexp2(s[j][1] - mn0);
            s[j][2] = fexp2(s[j][2] - mn1);
            s[j][3] = fexp2(s[j][3] - mn1);
            sum0 += s[j][0] + s[j][1];
            sum1 += s[j][2] + s[j][3];
        }
        sum0 += __shfl_xor_sync(0xffffffffu, sum0, 1);
        sum0 += __shfl_xor_sync(0xffffffffu, sum0, 2);
        sum1 += __shfl_xor_sync(0xffffffffu, sum1, 1);
        sum1 += __shfl_xor_sync(0xffffffffu, sum1, 2);
        l0 = l0 * a0 + sum0;
        l1 = l1 * a1 + sum1;
        #pragma unroll
        for (int j = 0; j < 8; j++) {
            o[j][0] *= a0; o[j][1] *= a0; o[j][2] *= a1; o[j][3] *= a1;
        }

        uint32_t pH[4][4], pL[4][4];
        #pragma unroll
        for (int kk = 0; kk < 4; kk++) {
            splitpack(s[2*kk][0],   s[2*kk][1],   pH[kk][0], pL[kk][0]);
            splitpack(s[2*kk][2],   s[2*kk][3],   pH[kk][1], pL[kk][1]);
            splitpack(s[2*kk+1][0], s[2*kk+1][1], pH[kk][2], pL[kk][2]);
            splitpack(s[2*kk+1][2], s[2*kk+1][3], pH[kk][3], pL[kk][3]);
        }

        #pragma unroll
        for (int kk = 0; kk < 4; kk++) {
            uint32_t th[4][4], tl[4][4];
            #pragma unroll
            for (int nb = 0; nb < 4; nb++) {
                uint32_t off = SWZ((kk * 16 + pv_row) * 128 + (nb * 16 + pv_col) * 2);
                LDM4T(th[nb][0], th[nb][1], th[nb][2], th[nb][3], uv_h + off);
                LDM4T(tl[nb][0], tl[nb][1], tl[nb][2], tl[nb][3], uv_l + off);
            }
            #pragma unroll
            for (int nb = 0; nb < 4; nb++) {
                uint32_t B0h[2] = {th[nb][0], th[nb][2]};
                uint32_t B1h[2] = {th[nb][1], th[nb][3]};
                uint32_t B0l[2] = {tl[nb][0], tl[nb][2]};
                uint32_t B1l[2] = {tl[nb][1], tl[nb][3]};
                MMA(o[2*nb],   pH[kk], B0h);
                MMA(o[2*nb],   pH[kk], B0l);
                MMA(o[2*nb],   pL[kk], B0h);
                MMA(o[2*nb+1], pH[kk], B1h);
                MMA(o[2*nb+1], pH[kk], B1l);
                MMA(o[2*nb+1], pL[kk], B1h);
            }
        }
    }

    float i0 = 1.f / l0, i1 = 1.f / l1;
    size_t r0 = (size_t)(b * TT + qi * 64 + w * 16 + g);
    #pragma unroll
    for (int j = 0; j < 8; j++) {
        int col = h * HDIM + j * 8 + tq * 2;
        split2_store(oh, ol, r0 * DM + col,       o[j][0] * i0, o[j][1] * i0);
        split2_store(oh, ol, (r0 + 8) * DM + col, o[j][2] * i1, o[j][3] * i1);
    }
}

// ---------------- launcher ----------------
extern "C" void kernel_launch(void* const* d_in, const int* in_sizes, int n_in,
                              void* d_out, int out_size) {
    const int*   idx    = (const int*)  d_in[0];
    const float* wte    = (const float*)d_in[1];
    const float* wpe    = (const float*)d_in[2];
    const float* ln1_w  = (const float*)d_in[3];
    const float* ln1_b  = (const float*)d_in[4];
    const float* caw    = (const float*)d_in[5];
    const float* cab    = (const float*)d_in[6];
    const float* cpw    = (const float*)d_in[7];
    const float* cpb    = (const float*)d_in[8];
    const float* ln2_w  = (const float*)d_in[9];
    const float* ln2_b  = (const float*)d_in[10];
    const float* cfw    = (const float*)d_in[11];
    const float* cfb    = (const float*)d_in[12];
    const float* swW    = (const float*)d_in[13];
    const float* swV    = (const float*)d_in[14];
    const float* swb    = (const float*)d_in[15];
    const float* swc    = (const float*)d_in[16];
    const float* mpw    = (const float*)d_in[17];
    const float* mpb    = (const float*)d_in[18];
    const float* lnf_w  = (const float*)d_in[19];
    const float* lnf_b  = (const float*)d_in[20];
    const float* lmw    = (const float*)d_in[21];
    float* out = (float*)d_out;

    float *x, *qkv, *a, *xf, *part;
    bf16 *xn_h, *xn_l, *att_h, *att_l, *h_h, *h_l, *c2_h, *c2_l;
    bf16 *wq_h, *wq_l, *wp_h, *wp_l, *wf_h, *wf_l, *wW_h, *wW_l, *wV_h, *wV_l, *wm_h, *wm_l;
    cudaGetSymbolAddress((void**)&x,    g_x);
    cudaGetSymbolAddress((void**)&qkv,  g_qkv);
    cudaGetSymbolAddress((void**)&a,    g_a);
    cudaGetSymbolAddress((void**)&xf,   g_xf);
    cudaGetSymbolAddress((void**)&part, g_part);
    cudaGetSymbolAddress((void**)&xn_h, g_xn_h);  cudaGetSymbolAddress((void**)&xn_l, g_xn_l);
    cudaGetSymbolAddress((void**)&att_h,g_att_h); cudaGetSymbolAddress((void**)&att_l,g_att_l);
    cudaGetSymbolAddress((void**)&h_h,  g_h_h);   cudaGetSymbolAddress((void**)&h_l,  g_h_l);
    cudaGetSymbolAddress((void**)&c2_h, g_c2_h);  cudaGetSymbolAddress((void**)&c2_l, g_c2_l);
    cudaGetSymbolAddress((void**)&wq_h, g_wq_h);  cudaGetSymbolAddress((void**)&wq_l, g_wq_l);
    cudaGetSymbolAddress((void**)&wp_h, g_wp_h);  cudaGetSymbolAddress((void**)&wp_l, g_wp_l);
    cudaGetSymbolAddress((void**)&wf_h, g_wf_h);  cudaGetSymbolAddress((void**)&wf_l, g_wf_l);
    cudaGetSymbolAddress((void**)&wW_h, g_wW_h);  cudaGetSymbolAddress((void**)&wW_l, g_wW_l);
    cudaGetSymbolAddress((void**)&wV_h, g_wV_h);  cudaGetSymbolAddress((void**)&wV_l, g_wV_l);
    cudaGetSymbolAddress((void**)&wm_h, g_wm_h);  cudaGetSymbolAddress((void**)&wm_l, g_wm_l);

    cudaFuncSetAttribute(attn_mma, cudaFuncAttributeMaxDynamicSharedMemorySize, ATSM);
    cudaFuncSetAttribute(gemm_mma<GM_F32>,    cudaFuncAttributeMaxDynamicSharedMemorySize, GSMEM);
    cudaFuncSetAttribute(gemm_mma<GM_RES>,    cudaFuncAttributeMaxDynamicSharedMemorySize, GSMEM);
    cudaFuncSetAttribute(gemm_mma<GM_SPLIT>,  cudaFuncAttributeMaxDynamicSharedMemorySize, GSMEM);
    cudaFuncSetAttribute(gemm_mma<GM_SWIGLU>, cudaFuncAttributeMaxDynamicSharedMemorySize, GSMEM);
    cudaFuncSetAttribute(gemm_mma<GM_PART>,   cudaFuncAttributeMaxDynamicSharedMemorySize, GSMEM);

    split_all<<<dim3(9216, 4), 256>>>(
        caw, wq_h, wq_l, NL * D3 * DM / 4,
        cpw, wp_h, wp_l, NL * DM * DM / 4,
        cfw, wf_h, wf_l, NL * D4 * DM / 4,
        mpw, wm_h, wm_l, NL * DM * D4 / 4);

    embed_kernel<<<BT, 192>>>(idx, wte, wpe, x);

    for (int l = 0; l < NL; l++) {
        size_t oq = (size_t)l * D3 * DM, op = (size_t)l * DM * DM;
        size_t of = (size_t)l * D4 * DM, ow = (size_t)l * D4 * D4, om = (size_t)l * DM * D4;
        ln_kernel<true><<<BT, 256>>>(x, DM, ln1_w + l * DM, ln1_b + l * DM, nullptr, xn_h, xn_l);
        gemm_mma<GM_F32><<<dim3(D3 / 128, BT / 128), 256, GSMEM>>>(
            xn_h, xn_l, wq_h + oq, wq_l + oq, cab + l * D3, nullptr, qkv, nullptr, nullptr,
            D3, DM, DM);
        attn_mma<<<dim3(TT / 64, BB * NHEAD), 128, ATSM>>>(qkv, att_h, att_l);
        gemm_mma<GM_RES><<<dim3(DM / 128, BT / 128), 256, GSMEM>>>(
            att_h, att_l, wp_h + op, wp_l + op, cpb + l * DM, nullptr, x, nullptr, nullptr,
            DM, DM, DM);
        ln_kernel<true><<<BT, 256>>>(x, DM, ln2_w + l * DM, ln2_b + l * DM, nullptr, xn_h, xn_l);
        if (l == 0) {
            transpose_all<<<dim3(D4 / 32, D4 / 32, 2 * NL), dim3(32, 8)>>>(
                swW, swV, wW_h, wW_l, wV_h, wV_l);
        }
        gemm_mma<GM_SPLIT><<<dim3(D4 / 128, BT / 128), 256, GSMEM>>>(
            xn_h, xn_l, wf_h + of, wf_l + of, cfb + l * D4, nullptr, nullptr, h_h, h_l,
            D4, DM, DM);
        gemm_mma<GM_F32><<<dim3(D4 / 128, BT / 128), 256, GSMEM>>>(
            h_h, h_l, wW_h + ow, wW_l + ow, swb + l * D4, nullptr, a, nullptr, nullptr,
            D4, D4, D4);
        gemm_mma<GM_SWIGLU><<<dim3(D4 / 128, BT / 128), 256, GSMEM>>>(
            h_h, h_l, wV_h + ow, wV_l + ow, swc + l * D4, a, nullptr, c2_h, c2_l,
            D4, D4, D4);
        // mlp_proj: split-K x2 (deterministic partial buffers + reduce)
        gemm_mma<GM_PART><<<dim3(DM / 128, BT / 128, 2), 256, GSMEM>>>(
            c2_h, c2_l, wm_h + om, wm_l + om, mpb + l * DM, nullptr, part, nullptr, nullptr,
            DM, D4 / 2, D4);
        addparts<<<(BT * DM / 4 + 255) / 256, 256>>>(x, part, BT * DM / 4);
    }

    ln_kernel<false><<<BB, 256>>>(x + (size_t)(TT - 1) * DM, (size_t)TT * DM,
                                  lnf_w, lnf_b, xf, nullptr, nullptr);
    sgemm_kernel<<<dim3(VV / 128, 1), 256>>>(xf, lmw, out, BB, VV, DM);
}

// round 14
// speedup vs baseline: 1.1216x; 1.0741x over previous
#include <cuda_runtime.h>
#include <cuda_bf16.h>
#include <math.h>
#include <stdint.h>

#define BB 4
#define TT 1024
#define DM 768
#define NHEAD 12
#define HDIM 64
#define NL 4
#define VV 50304
#define D3 2304
#define D4 3072
#define BT 4096   // B*T

typedef __nv_bfloat16 bf16;

// ---------------- scratch (device globals; no allocation anywhere) ----------------
__device__ float g_x  [BT * DM];
__device__ float g_qkv[BT * D3];
__device__ float g_a  [BT * D4];
__device__ float g_c2f[BT * D4];
__device__ float g_xf [BB * DM];
__device__ float g_part[2 * BT * DM];     // split-K partials
__device__ bf16 g_xn_h [BT * DM],  g_xn_l [BT * DM];
__device__ bf16 g_att_h[BT * DM],  g_att_l[BT * DM];
__device__ bf16 g_h_h  [BT * D4],  g_h_l  [BT * D4];
__device__ bf16 g_c2_h [BT * D4],  g_c2_l [BT * D4];
// split-bf16 weights, all stored [N][K] (K contiguous)
__device__ bf16 g_wq_h[NL * D3 * DM], g_wq_l[NL * D3 * DM];
__device__ bf16 g_wp_h[NL * DM * DM], g_wp_l[NL * DM * DM];
__device__ bf16 g_wf_h[NL * D4 * DM], g_wf_l[NL * D4 * DM];
__device__ bf16 g_wW_h[NL * D4 * D4], g_wW_l[NL * D4 * D4];
__device__ bf16 g_wV_h[NL * D4 * D4], g_wV_l[NL * D4 * D4];
__device__ bf16 g_wm_h[NL * DM * D4], g_wm_l[NL * DM * D4];

// ================= asm helpers (base sm_103 features only) =================
__device__ __forceinline__ uint32_t smem_u32(const void* p) {
    uint32_t a;
    asm("{ .reg .u64 t; cvta.to.shared.u64 t, %1; cvt.u32.u64 %0, t; }" : "=r"(a) : "l"(p));
    return a;
}
__device__ __forceinline__ float fexp2(float x) {
    float r;
    asm("ex2.approx.ftz.f32 %0, %1;" : "=f"(r) : "f"(x));
    return r;
}
#define SWZ(off) ((off) ^ (((off) >> 3) & 0x70))

#define CP16(dst, src) \
    asm volatile("cp.async.cg.shared.global [%0], [%1], 16;" :: "r"(dst), "l"(src) : "memory")
#define CP_COMMIT() asm volatile("cp.async.commit_group;" ::: "memory")
#define CP_WAIT1()  asm volatile("cp.async.wait_group 1;"  ::: "memory")

#define LDM4(r0, r1, r2, r3, addr) \
    asm volatile("ldmatrix.sync.aligned.m8n8.x4.shared.b16 {%0,%1,%2,%3}, [%4];" \
                 : "=r"(r0), "=r"(r1), "=r"(r2), "=r"(r3) : "r"(addr))

#define LDM4T(r0, r1, r2, r3, addr) \
    asm volatile("ldmatrix.sync.aligned.m8n8.x4.trans.shared.b16 {%0,%1,%2,%3}, [%4];" \
                 : "=r"(r0), "=r"(r1), "=r"(r2), "=r"(r3) : "r"(addr))

#define MMA(D, A, B) \
    asm volatile("mma.sync.aligned.m16n8k16.row.col.f32.bf16.bf16.f32 " \
                 "{%0,%1,%2,%3}, {%4,%5,%6,%7}, {%8,%9}, {%0,%1,%2,%3};" \
                 : "+f"((D)[0]), "+f"((D)[1]), "+f"((D)[2]), "+f"((D)[3]) \
                 : "r"((A)[0]), "r"((A)[1]), "r"((A)[2]), "r"((A)[3]), \
                   "r"((B)[0]), "r"((B)[1]))

__device__ __forceinline__ void split2_store(bf16* H, bf16* L, size_t off, float v0, float v1) {
    bf16 h0 = __float2bfloat16(v0), h1 = __float2bfloat16(v1);
    bf16 l0 = __float2bfloat16(v0 - __bfloat162float(h0));
    bf16 l1 = __float2bfloat16(v1 - __bfloat162float(h1));
    *(__nv_bfloat162*)(H + off) = __halves2bfloat162(h0, h1);
    *(__nv_bfloat162*)(L + off) = __halves2bfloat162(l0, l1);
}

__device__ __forceinline__ void split4(float4 v, uint2& hp, uint2& lp) {
    bf16 a = __float2bfloat16(v.x), b = __float2bfloat16(v.y);
    bf16 c = __float2bfloat16(v.z), d = __float2bfloat16(v.w);
    bf16 e = __float2bfloat16(v.x - __bfloat162float(a));
    bf16 f = __float2bfloat16(v.y - __bfloat162float(b));
    bf16 g = __float2bfloat16(v.z - __bfloat162float(c));
    bf16 k = __float2bfloat16(v.w - __bfloat162float(d));
    hp.x = (uint32_t)__bfloat16_as_ushort(a) | ((uint32_t)__bfloat16_as_ushort(b) << 16);
    hp.y = (uint32_t)__bfloat16_as_ushort(c) | ((uint32_t)__bfloat16_as_ushort(d) << 16);
    lp.x = (uint32_t)__bfloat16_as_ushort(e) | ((uint32_t)__bfloat16_as_ushort(f) << 16);
    lp.y = (uint32_t)__bfloat16_as_ushort(g) | ((uint32_t)__bfloat16_as_ushort(k) << 16);
}

__device__ __forceinline__ void splitpack(float x, float y, uint32_t& hi, uint32_t& lo) {
    bf16 xh = __float2bfloat16(x), yh = __float2bfloat16(y);
    bf16 xl = __float2bfloat16(x - __bfloat162float(xh));
    bf16 yl = __float2bfloat16(y - __bfloat162float(yh));
    hi = (uint32_t)__bfloat16_as_ushort(xh) | ((uint32_t)__bfloat16_as_ushort(yh) << 16);
    lo = (uint32_t)__bfloat16_as_ushort(xl) | ((uint32_t)__bfloat16_as_ushort(yl) << 16);
}

// ---------------- weight conversion ----------------
__global__ void split_all(const float* __restrict__ s0, bf16* h0, bf16* l0, int n0,
                          const float* __restrict__ s1, bf16* h1, bf16* l1, int n1,
                          const float* __restrict__ s2, bf16* h2, bf16* l2, int n2,
                          const float* __restrict__ s3, bf16* h3, bf16* l3, int n3) {
    const float* s; bf16 *h, *l; int n;
    switch (blockIdx.y) {
        case 0: s = s0; h = h0; l = l0; n = n0; break;
        case 1: s = s1; h = h1; l = l1; n = n1; break;
        case 2: s = s2; h = h2; l = l2; n = n2; break;
        default:s = s3; h = h3; l = l3; n = n3; break;
    }
    int i = blockIdx.x * blockDim.x + threadIdx.x;
    if (i >= n) return;
    float4 v = ((const float4*)s)[i];
    split2_store(h, l, (size_t)i * 4,     v.x, v.y);
    split2_store(h, l, (size_t)i * 4 + 2, v.z, v.w);
}

__global__ void transpose_all(const float* __restrict__ W, const float* __restrict__ V,
                              bf16* __restrict__ Wh, bf16* __restrict__ Wl,
                              bf16* __restrict__ Vh, bf16* __restrict__ Vl) {
    __shared__ float t[32][33];
    int z = blockIdx.z;
    int l = (z < NL) ? z : z - NL;
    const float* s = ((z < NL) ? W : V) + (size_t)l * D4 * D4;
    bf16* H = ((z < NL) ? Wh : Vh) + (size_t)l * D4 * D4;
    bf16* L = ((z < NL) ? Wl : Vl) + (size_t)l * D4 * D4;
    int n0 = blockIdx.x * 32, k0 = blockIdx.y * 32;
    int cx = threadIdx.x;
    #pragma unroll
    for (int r = threadIdx.y; r < 32; r += 8)
        t[r][cx] = s[(size_t)(k0 + r) * D4 + n0 + cx];
    __syncthreads();
    #pragma unroll
    for (int r = threadIdx.y; r < 32; r += 8) {
        float v = t[cx][r];
        size_t off = (size_t)(n0 + r) * D4 + k0 + cx;
        bf16 h = __float2bfloat16(v);
        H[off] = h;
        L[off] = __float2bfloat16(v - __bfloat162float(h));
    }
}

// ---------------- embedding ----------------
__global__ void embed_kernel(const int* __restrict__ idx, const float* __restrict__ wte,
                             const float* __restrict__ wpe, float* __restrict__ x) {
    int bt = blockIdx.x;
    int t  = bt & (TT - 1);
    int tok = idx[bt];
    int c = threadIdx.x * 4;
    float4 a = *(const float4*)&wte[(size_t)tok * DM + c];
    float4 p = *(const float4*)&wpe[(size_t)t   * DM + c];
    a.x += p.x; a.y += p.y; a.z += p.z; a.w += p.w;
    *(float4*)&x[(size_t)bt * DM + c] = a;
}

// ---------------- split-K partial reduce: x += p0 + p1 ----------------
__global__ void addparts(float* __restrict__ x, const float* __restrict__ p, int n4) {
    int i = blockIdx.x * blockDim.x + threadIdx.x;
    if (i >= n4) return;
    float4 xv = ((const float4*)x)[i];
    float4 a = ((const float4*)p)[i];
    float4 b = ((const float4*)(p + (size_t)BT * DM))[i];
    xv.x += a.x + b.x; xv.y += a.y + b.y; xv.z += a.z + b.z; xv.w += a.w + b.w;
    ((float4*)x)[i] = xv;
}

// ---------------- elementwise swiglu + split: (h,l) = split(swish(a) * c2f) -------
__global__ void swiglu_split(const float* __restrict__ a, const float* __restrict__ c2f,
                             bf16* __restrict__ H, bf16* __restrict__ L, int n4) {
    int i = blockIdx.x * blockDim.x + threadIdx.x;
    if (i >= n4) return;
    float4 g = ((const float4*)a)[i];
    float4 v = ((const float4*)c2f)[i];
    float o0 = g.x / (1.f + __expf(-g.x)) * v.x;
    float o1 = g.y / (1.f + __expf(-g.y)) * v.y;
    float o2 = g.z / (1.f + __expf(-g.z)) * v.z;
    float o3 = g.w / (1.f + __expf(-g.w)) * v.w;
    split2_store(H, L, (size_t)i * 4,     o0, o1);
    split2_store(H, L, (size_t)i * 4 + 2, o2, o3);
}

// ---------------- layernorm ----------------
template <bool SPLIT>
__global__ __launch_bounds__(256)
void ln_kernel(const float* __restrict__ x, size_t rstride,
               const float* __restrict__ w, const float* __restrict__ b,
               float* __restrict__ yf, bf16* __restrict__ yh, bf16* __restrict__ yl) {
    const float* xr = x + (size_t)blockIdx.x * rstride;
    int tid = threadIdx.x;

    float v0 = xr[tid], v1 = xr[tid + 256], v2 = xr[tid + 512];
    float s  = v0 + v1 + v2;
    float s2 = v0 * v0 + v1 * v1 + v2 * v2;
    #pragma unroll
    for (int off = 16; off; off >>= 1) {
        s  += __shfl_xor_sync(0xffffffffu, s,  off);
        s2 += __shfl_xor_sync(0xffffffffu, s2, off);
    }
    __shared__ float sh_s[8], sh_s2[8];
    int wid = tid >> 5, lane = tid & 31;
    if (lane == 0) { sh_s[wid] = s; sh_s2[wid] = s2; }
    __syncthreads();
    float tot = 0.f, tot2 = 0.f;
    #pragma unroll
    for (int i = 0; i < 8; i++) { tot += sh_s[i]; tot2 += sh_s2[i]; }
    const float inv = 1.0f / (float)DM;
    float mean = tot * inv;
    float var  = tot2 * inv - mean * mean;
    float rstd = rsqrtf(var + 1e-5f);

    size_t base = (size_t)blockIdx.x * DM;
    float o0 = (v0 - mean) * rstd * w[tid]       + b[tid];
    float o1 = (v1 - mean) * rstd * w[tid + 256] + b[tid + 256];
    float o2 = (v2 - mean) * rstd * w[tid + 512] + b[tid + 512];
    if (SPLIT) {
        bf16 h0 = __float2bfloat16(o0);
        yh[base + tid] = h0;       yl[base + tid]       = __float2bfloat16(o0 - __bfloat162float(h0));
        bf16 h1 = __float2bfloat16(o1);
        yh[base + tid + 256] = h1; yl[base + tid + 256] = __float2bfloat16(o1 - __bfloat162float(h1));
        bf16 h2 = __float2bfloat16(o2);
        yh[base + tid + 512] = h2; yl[base + tid + 512] = __float2bfloat16(o2 - __bfloat162float(h2));
    } else {
        yf[base + tid]       = o0;
        yf[base + tid + 256] = o1;
        yf[base + tid + 512] = o2;
    }
}

// ================= mma.sync split-bf16 GEMM =================
#define GM_F32    0
#define GM_RES    1
#define GM_SPLIT  2
#define GM_PART   3   // split-K partial: +bias on z==0, write Cf + z*BT*DM
#define GM_DUAL   4   // z selects (B,bias,Cf) vs (B2,bias2,Cf2); fp32 out

#define GSTAGE 65536
#define GSMEM  (3 * GSTAGE + 1024)

struct Frags {
    uint32_t aH[2][4], aL[2][4], bH[8][2], bL[8][2];
};

template <int MODE>
__global__ __launch_bounds__(256, 1)
void gemm_mma(const bf16* __restrict__ Ah, const bf16* __restrict__ Al,
              const bf16* __restrict__ Bh, const bf16* __restrict__ Bl,
              const float* __restrict__ bias,
              float* __restrict__ Cf, bf16* __restrict__ Ch, bf16* __restrict__ Cl,
              const bf16* __restrict__ B2h, const bf16* __restrict__ B2l,
              const float* __restrict__ bias2, float* __restrict__ Cf2,
              int N, int K, int lda) {
    extern __shared__ char dyn[];
    uint32_t base = (smem_u32(dyn) + 1023) & ~1023u;

    const int tid = threadIdx.x;
    const int bm = blockIdx.y * 128, bn = blockIdx.x * 128;
    const int koff = (MODE == GM_PART) ? blockIdx.z * K : 0;
    const int lane = tid & 31, wid = tid >> 5;
    const int wm = wid & 3, wn = wid >> 2;

    const bf16* Bh_ = Bh;
    const bf16* Bl_ = Bl;
    const float* bias_ = bias;
    float* Cf_ = Cf;
    if (MODE == GM_DUAL && blockIdx.z) { Bh_ = B2h; Bl_ = B2l; bias_ = bias2; Cf_ = Cf2; }

    const int lr = ((lane >> 3) & 1) * 8 + (lane & 7);
    const int lk = lane >> 4;

    float d[2][8][4];
    #pragma unroll
    for (int i = 0; i < 2; i++)
        #pragma unroll
        for (int j = 0; j < 8; j++)
            #pragma unroll
            for (int q = 0; q < 4; q++) d[i][j][q] = 0.f;

    const int nkt = K >> 6;

    auto load_stage = [&](int kt, int sb) {
        uint32_t st = base + sb * GSTAGE;
        int k0 = koff + (kt << 6);
        #pragma unroll
        for (int i = 0; i < 4; i++) {
            int row = (tid >> 3) + i * 32;
            int seg = tid & 7;
            uint32_t soff = SWZ(row * 128 + seg * 16);
            size_t ga = (size_t)(bm + row) * lda + k0 + seg * 8;
            size_t gb = (size_t)(bn + row) * lda + k0 + seg * 8;
            CP16(st + soff,         Ah + ga);
            CP16(st + 16384 + soff, Al + ga);
            CP16(st + 32768 + soff, Bh_ + gb);
            CP16(st + 49152 + soff, Bl_ + gb);
        }
    };

    auto load_frags = [&](uint32_t st, int ks, Frags& f) {
        #pragma unroll
        for (int am = 0; am < 2; am++) {
            int row = wm * 32 + am * 16 + lr;
            uint32_t off = SWZ(row * 128 + (ks * 2 + lk) * 16);
            LDM4(f.aH[am][0], f.aH[am][1], f.aH[am][2], f.aH[am][3], st + off);
            LDM4(f.aL[am][0], f.aL[am][1], f.aL[am][2], f.aL[am][3], st + 16384 + off);
        }
        #pragma unroll
        for (int nb = 0; nb < 4; nb++) {
            int row = wn * 64 + nb * 16 + lr;
            uint32_t off = SWZ(row * 128 + (ks * 2 + lk) * 16);
            uint32_t t0, t1, t2, t3;
            LDM4(t0, t1, t2, t3, st + 32768 + off);
            f.bH[2*nb][0] = t0; f.bH[2*nb][1] = t2; f.bH[2*nb+1][0] = t1; f.bH[2*nb+1][1] = t3;
            LDM4(t0, t1, t2, t3, st + 49152 + off);
            f.bL[2*nb][0] = t0; f.bL[2*nb][1] = t2; f.bL[2*nb+1][0] = t1; f.bL[2*nb+1][1] = t3;
        }
    };
    auto do_mma = [&](Frags& f) {
        #pragma unroll
        for (int am = 0; am < 2; am++)
            #pragma unroll
            for (int an = 0; an < 8; an++) {
                MMA(d[am][an], f.aH[am], f.bH[an]);
                MMA(d[am][an], f.aH[am], f.bL[an]);
                MMA(d[am][an], f.aL[am], f.bH[an]);
            }
    };

    load_stage(0, 0); CP_COMMIT();
    load_stage(1, 1); CP_COMMIT();

    Frags fr[2];
    for (int kt = 0; kt < nkt; kt++) {
        CP_WAIT1();
        __syncthreads();
        if (kt + 2 < nkt) load_stage(kt + 2, (kt + 2) % 3);
        CP_COMMIT();

        uint32_t st = base + (kt % 3) * GSTAGE;
        load_frags(st, 0, fr[0]);
        #pragma unroll
        for (int ks = 0; ks < 4; ks++) {
            if (ks < 3) load_frags(st, ks + 1, fr[(ks + 1) & 1]);
            do_mma(fr[ks & 1]);
        }
    }

    const int g = lane >> 2, tq = lane & 3;
    #pragma unroll
    for (int am = 0; am < 2; am++)
        #pragma unroll
        for (int an = 0; an < 8; an++) {
            int r0 = bm + wm * 32 + am * 16 + g;
            int c  = bn + wn * 64 + an * 8 + tq * 2;
            #pragma unroll
            for (int half = 0; half < 2; half++) {
                int row = r0 + half * 8;
                float v0 = d[am][an][half * 2];
                float v1 = d[am][an][half * 2 + 1];
                if (MODE != GM_PART || blockIdx.z == 0) { v0 += bias_[c]; v1 += bias_[c + 1]; }
                size_t off = (size_t)row * N + c;
                if (MODE == GM_F32 || MODE == GM_DUAL) {
                    *(float2*)(Cf_ + off) = make_float2(v0, v1);
                } else if (MODE == GM_RES) {
                    float2 o = *(const float2*)(Cf_ + off);
                    *(float2*)(Cf_ + off) = make_float2(v0 + o.x, v1 + o.y);
                } else if (MODE == GM_SPLIT) {
                    split2_store(Ch, Cl, off, v0, v1);
                } else {  // GM_PART
                    *(float2*)(Cf_ + (size_t)blockIdx.z * BT * DM + off) = make_float2(v0, v1);
                }
            }
        }
}

// ---------------- SIMT sgemm (lm_head only, M=4) ----------------
__global__ __launch_bounds__(256)
void sgemm_kernel(const float* __restrict__ A, const float* __restrict__ B,
                  float* __restrict__ C, int M, int N, int K) {
    __shared__ float As[8 * 128];
    __shared__ float Bs[8 * 128];

    const int tid = threadIdx.x;
    const int tx = tid & 15, ty = tid >> 4;
    const int bm = blockIdx.y * 128, bn = blockIdx.x * 128;

    float acc[8][8];
    #pragma unroll
    for (int i = 0; i < 8; i++)
        #pragma unroll
        for (int j = 0; j < 8; j++) acc[i][j] = 0.f;

    const int arow = tid >> 1;
    const int acol = (tid & 1) * 4;

    for (int k0 = 0; k0 < K; k0 += 8) {
        float4 av = make_float4(0.f, 0.f, 0.f, 0.f);
        if (bm + arow < M)
            av = *(const float4*)&A[(size_t)(bm + arow) * K + k0 + acol];
        As[(acol + 0) * 128 + arow] = av.x;
        As[(acol + 1) * 128 + arow] = av.y;
        As[(acol + 2) * 128 + arow] = av.z;
        As[(acol + 3) * 128 + arow] = av.w;
        float4 bv = *(const float4*)&B[(size_t)(bn + arow) * K + k0 + acol];
        Bs[(acol + 0) * 128 + arow] = bv.x;
        Bs[(acol + 1) * 128 + arow] = bv.y;
        Bs[(acol + 2) * 128 + arow] = bv.z;
        Bs[(acol + 3) * 128 + arow] = bv.w;
        __syncthreads();

        #pragma unroll
        for (int kk = 0; kk < 8; kk++) {
            float a[8], b[8];
            *(float4*)&a[0] = *(const float4*)&As[kk * 128 + ty * 8];
            *(float4*)&a[4] = *(const float4*)&As[kk * 128 + ty * 8 + 4];
            *(float4*)&b[0] = *(const float4*)&Bs[kk * 128 + tx * 8];
            *(float4*)&b[4] = *(const float4*)&Bs[kk * 128 + tx * 8 + 4];
            #pragma unroll
            for (int i = 0; i < 8; i++)
                #pragma unroll
                for (int j = 0; j < 8; j++)
                    acc[i][j] = fmaf(a[i], b[j], acc[i][j]);
        }
        __syncthreads();
    }

    #pragma unroll
    for (int i = 0; i < 8; i++) {
        int row = bm + ty * 8 + i;
        if (row >= M) continue;
        #pragma unroll
        for (int j = 0; j < 8; j++)
            C[(size_t)row * N + bn + tx * 8 + j] = acc[i][j];
    }
}

// ================= HMMA flash attention (split-bf16, causal, HD=64) =================
#define ATSM (6 * 8192)

__global__ __launch_bounds__(128)
void attn_mma(const float* __restrict__ qkv, bf16* __restrict__ oh, bf16* __restrict__ ol) {
    extern __shared__ char smn[];
    char* sq_h = smn;            char* sq_l = smn + 8192;
    char* sk_h = smn + 16384;    char* sk_l = smn + 24576;
    char* sv_h = smn + 32768;    char* sv_l = smn + 40960;
    const uint32_t uq_h = smem_u32(smn);
    const uint32_t uq_l = uq_h + 8192;
    const uint32_t uk_h = uq_h + 16384, uk_l = uq_h + 24576;
    const uint32_t uv_h = uq_h + 32768, uv_l = uq_h + 40960;

    const int tid = threadIdx.x;
    const int lane = tid & 31, w = tid >> 5;
    const int qi = blockIdx.x;
    const int b = blockIdx.y / NHEAD, h = blockIdx.y % NHEAD;
    const int lr = ((lane >> 3) & 1) * 8 + (lane & 7);
    const int lk = lane >> 4;
    const int g = lane >> 2, tq = lane & 3;
    const int gi = lane >> 3;
    const int pv_row = ((gi >> 1) & 1) * 8 + (lane & 7);
    const int pv_col = (gi & 1) * 8;

    const float SC = 0.18033688011112042f;   // 0.125 * log2(e)

    #pragma unroll
    for (int it = 0; it < 8; it++) {
        int i = tid + it * 128;
        int row = i >> 4, c4 = (i & 15) * 4;
        float4 v = *(const float4*)&qkv[(size_t)(b * TT + qi * 64 + row) * D3 + h * HDIM + c4];
        uint2 hp, lp; split4(v, hp, lp);
        uint32_t off = SWZ(row * 128 + c4 * 2);
        *(uint2*)(sq_h + off) = hp;
        *(uint2*)(sq_l + off) = lp;
    }
    __syncthreads();

    uint32_t qAh[4][4], qAl[4][4];
    #pragma unroll
    for (int kk = 0; kk < 4; kk++) {
        uint32_t off = SWZ((w * 16 + lr) * 128 + (kk * 2 + lk) * 16);
        LDM4(qAh[kk][0], qAh[kk][1], qAh[kk][2], qAh[kk][3], uq_h + off);
        LDM4(qAl[kk][0], qAl[kk][1], qAl[kk][2], qAl[kk][3], uq_l + off);
    }

    float m0 = -1e30f, m1 = -1e30f, l0 = 0.f, l1 = 0.f;
    float o[8][4];
    #pragma unroll
    for (int j = 0; j < 8; j++)
        #pragma unroll
        for (int q = 0; q < 4; q++) o[j][q] = 0.f;

    const int rg0 = qi * 64 + w * 16 + g;

    for (int kt = 0; kt <= qi; kt++) {
        __syncthreads();
        #pragma unroll
        for (int it = 0; it < 8; it++) {
            int i = tid + it * 128;
            int row = i >> 4, c4 = (i & 15) * 4;
            size_t gbase = (size_t)(b * TT + kt * 64 + row) * D3 + h * HDIM + c4;
            float4 kv = *(const float4*)&qkv[gbase + DM];
            float4 vv = *(const float4*)&qkv[gbase + 2 * DM];
            uint32_t off = SWZ(row * 128 + c4 * 2);
            uint2 hp, lp;
            split4(kv, hp, lp);
            *(uint2*)(sk_h + off) = hp;
            *(uint2*)(sk_l + off) = lp;
            split4(vv, hp, lp);
            *(uint2*)(sv_h + off) = hp;
            *(uint2*)(sv_l + off) = lp;
        }
        __syncthreads();

        float s[8][4];
        #pragma unroll
        for (int j = 0; j < 8; j++)
            #pragma unroll
            for (int q = 0; q < 4; q++) s[j][q] = 0.f;

        #pragma unroll
        for (int kk = 0; kk < 4; kk++) {
            uint32_t th[4][4], tl[4][4];
            #pragma unroll
            for (int nb = 0; nb < 4; nb++) {
                uint32_t off = SWZ((nb * 16 + lr) * 128 + (kk * 2 + lk) * 16);
                LDM4(th[nb][0], th[nb][1], th[nb][2], th[nb][3], uk_h + off);
                LDM4(tl[nb][0], tl[nb][1], tl[nb][2], tl[nb][3], uk_l + off);
            }
            #pragma unroll
            for (int nb = 0; nb < 4; nb++) {
                uint32_t B0h[2] = {th[nb][0], th[nb][2]};
                uint32_t B1h[2] = {th[nb][1], th[nb][3]};
                uint32_t B0l[2] = {tl[nb][0], tl[nb][2]};
                uint32_t B1l[2] = {tl[nb][1], tl[nb][3]};
                MMA(s[2*nb],   qAh[kk], B0h);
                MMA(s[2*nb],   qAh[kk], B0l);
                MMA(s[2*nb],   qAl[kk], B0h);
                MMA(s[2*nb+1], qAh[kk], B1h);
                MMA(s[2*nb+1], qAh[kk], B1l);
                MMA(s[2*nb+1], qAl[kk], B1h);
            }
        }

        #pragma unroll
        for (int j = 0; j < 8; j++) {
            s[j][0] *= SC; s[j][1] *= SC; s[j][2] *= SC; s[j][3] *= SC;
        }
        if (kt == qi) {
            #pragma unroll
            for (int j = 0; j < 8; j++) {
                int col = kt * 64 + j * 8 + tq * 2;
                if (col     > rg0)     s[j][0] = -1e30f;
                if (col + 1 > rg0)     s[j][1] = -1e30f;
                if (col     > rg0 + 8) s[j][2] = -1e30f;
                if (col + 1 > rg0 + 8) s[j][3] = -1e30f;
            }
        }

        float mt0 = -1e30f, mt1 = -1e30f;
        #pragma unroll
        for (int j = 0; j < 8; j++) {
            mt0 = fmaxf(mt0, fmaxf(s[j][0], s[j][1]));
            mt1 = fmaxf(mt1, fmaxf(s[j][2], s[j][3]));
        }
        mt0 = fmaxf(mt0, __shfl_xor_sync(0xffffffffu, mt0, 1));
        mt0 = fmaxf(mt0, __shfl_xor_sync(0xffffffffu, mt0, 2));
        mt1 = fmaxf(mt1, __shfl_xor_sync(0xffffffffu, mt1, 1));
        mt1 = fmaxf(mt1, __shfl_xor_sync(0xffffffffu, mt1, 2));
        float mn0 = fmaxf(m0, mt0), mn1 = fmaxf(m1, mt1);
        float a0 = fexp2(m0 - mn0), a1 = fexp2(m1 - mn1);
        m0 = mn0; m1 = mn1;

        float sum0 = 0.f, sum1 = 0.f;
        #pragma unroll
        for (int j = 0; j < 8; j++) {
            s[j][0] = fexp2(s[j][0] - mn0);
            s[j][1] = fexp2(s[j][1] - mn0);
            s[j][2] = fexp2(s[j][2] - mn1);
            s[j][3] = fexp2(s[j][3] - mn1);
            sum0 += s[j][0] + s[j][1];
            sum1 += s[j][2] + s[j][3];
        }
        sum0 += __shfl_xor_sync(0xffffffffu, sum0, 1);
        sum0 += __shfl_xor_sync(0xffffffffu, sum0, 2);
        sum1 += __shfl_xor_sync(0xffffffffu, sum1, 1);
        sum1 += __shfl_xor_sync(0xffffffffu, sum1, 2);
        l0 = l0 * a0 + sum0;
        l1 = l1 * a1 + sum1;
        #pragma unroll
        for (int j = 0; j < 8; j++) {
            o[j][0] *= a0; o[j][1] *= a0; o[j][2] *= a1; o[j][3] *= a1;
        }

        uint32_t pH[4][4], pL[4][4];
        #pragma unroll
        for (int kk = 0; kk < 4; kk++) {
            splitpack(s[2*kk][0],   s[2*kk][1],   pH[kk][0], pL[kk][0]);
            splitpack(s[2*kk][2],   s[2*kk][3],   pH[kk][1], pL[kk][1]);
            splitpack(s[2*kk+1][0], s[2*kk+1][1], pH[kk][2], pL[kk][2]);
            splitpack(s[2*kk+1][2], s[2*kk+1][3], pH[kk][3], pL[kk][3]);
        }

        #pragma unroll
        for (int kk = 0; kk < 4; kk++) {
            uint32_t th[4][4], tl[4][4];
            #pragma unroll
            for (int nb = 0; nb < 4; nb++) {
                uint32_t off = SWZ((kk * 16 + pv_row) * 128 + (nb * 16 + pv_col) * 2);
                LDM4T(th[nb][0], th[nb][1], th[nb][2], th[nb][3], uv_h + off);
                LDM4T(tl[nb][0], tl[nb][1], tl[nb][2], tl[nb][3], uv_l + off);
            }
            #pragma unroll
            for (int nb = 0; nb < 4; nb++) {
                uint32_t B0h[2] = {th[nb][0], th[nb][2]};
                uint32_t B1h[2] = {th[nb][1], th[nb][3]};
                uint32_t B0l[2] = {tl[nb][0], tl[nb][2]};
                uint32_t B1l[2] = {tl[nb][1], tl[nb][3]};
                MMA(o[2*nb],   pH[kk], B0h);
                MMA(o[2*nb],   pH[kk], B0l);
                MMA(o[2*nb],   pL[kk], B0h);
                MMA(o[2*nb+1], pH[kk], B1h);
                MMA(o[2*nb+1], pH[kk], B1l);
                MMA(o[2*nb+1], pL[kk], B1h);
            }
        }
    }

    float i0 = 1.f / l0, i1 = 1.f / l1;
    size_t r0 = (size_t)(b * TT + qi * 64 + w * 16 + g);
    #pragma unroll
    for (int j = 0; j < 8; j++) {
        int col = h * HDIM + j * 8 + tq * 2;
        split2_store(oh, ol, r0 * DM + col,       o[j][0] * i0, o[j][1] * i0);
        split2_store(oh, ol, (r0 + 8) * DM + col, o[j][2] * i1, o[j][3] * i1);
    }
}

// ---------------- launcher ----------------
extern "C" void kernel_launch(void* const* d_in, const int* in_sizes, int n_in,
                              void* d_out, int out_size) {
    const int*   idx    = (const int*)  d_in[0];
    const float* wte    = (const float*)d_in[1];
    const float* wpe    = (const float*)d_in[2];
    const float* ln1_w  = (const float*)d_in[3];
    const float* ln1_b  = (const float*)d_in[4];
    const float* caw    = (const float*)d_in[5];
    const float* cab    = (const float*)d_in[6];
    const float* cpw    = (const float*)d_in[7];
    const float* cpb    = (const float*)d_in[8];
    const float* ln2_w  = (const float*)d_in[9];
    const float* ln2_b  = (const float*)d_in[10];
    const float* cfw    = (const float*)d_in[11];
    const float* cfb    = (const float*)d_in[12];
    const float* swW    = (const float*)d_in[13];
    const float* swV    = (const float*)d_in[14];
    const float* swb    = (const float*)d_in[15];
    const float* swc    = (const float*)d_in[16];
    const float* mpw    = (const float*)d_in[17];
    const float* mpb    = (const float*)d_in[18];
    const float* lnf_w  = (const float*)d_in[19];
    const float* lnf_b  = (const float*)d_in[20];
    const float* lmw    = (const float*)d_in[21];
    float* out = (float*)d_out;

    float *x, *qkv, *a, *c2f, *xf, *part;
    bf16 *xn_h, *xn_l, *att_h, *att_l, *h_h, *h_l, *c2_h, *c2_l;
    bf16 *wq_h, *wq_l, *wp_h, *wp_l, *wf_h, *wf_l, *wW_h, *wW_l, *wV_h, *wV_l, *wm_h, *wm_l;
    cudaGetSymbolAddress((void**)&x,    g_x);
    cudaGetSymbolAddress((void**)&qkv,  g_qkv);
    cudaGetSymbolAddress((void**)&a,    g_a);
    cudaGetSymbolAddress((void**)&c2f,  g_c2f);
    cudaGetSymbolAddress((void**)&xf,   g_xf);
    cudaGetSymbolAddress((void**)&part, g_part);
    cudaGetSymbolAddress((void**)&xn_h, g_xn_h);  cudaGetSymbolAddress((void**)&xn_l, g_xn_l);
    cudaGetSymbolAddress((void**)&att_h,g_att_h); cudaGetSymbolAddress((void**)&att_l,g_att_l);
    cudaGetSymbolAddress((void**)&h_h,  g_h_h);   cudaGetSymbolAddress((void**)&h_l,  g_h_l);
    cudaGetSymbolAddress((void**)&c2_h, g_c2_h);  cudaGetSymbolAddress((void**)&c2_l, g_c2_l);
    cudaGetSymbolAddress((void**)&wq_h, g_wq_h);  cudaGetSymbolAddress((void**)&wq_l, g_wq_l);
    cudaGetSymbolAddress((void**)&wp_h, g_wp_h);  cudaGetSymbolAddress((void**)&wp_l, g_wp_l);
    cudaGetSymbolAddress((void**)&wf_h, g_wf_h);  cudaGetSymbolAddress((void**)&wf_l, g_wf_l);
    cudaGetSymbolAddress((void**)&wW_h, g_wW_h);  cudaGetSymbolAddress((void**)&wW_l, g_wW_l);
    cudaGetSymbolAddress((void**)&wV_h, g_wV_h);  cudaGetSymbolAddress((void**)&wV_l, g_wV_l);
    cudaGetSymbolAddress((void**)&wm_h, g_wm_h);  cudaGetSymbolAddress((void**)&wm_l, g_wm_l);

    cudaFuncSetAttribute(attn_mma, cudaFuncAttributeMaxDynamicSharedMemorySize, ATSM);
    cudaFuncSetAttribute(gemm_mma<GM_F32>,   cudaFuncAttributeMaxDynamicSharedMemorySize, GSMEM);
    cudaFuncSetAttribute(gemm_mma<GM_RES>,   cudaFuncAttributeMaxDynamicSharedMemorySize, GSMEM);
    cudaFuncSetAttribute(gemm_mma<GM_SPLIT>, cudaFuncAttributeMaxDynamicSharedMemorySize, GSMEM);
    cudaFuncSetAttribute(gemm_mma<GM_PART>,  cudaFuncAttributeMaxDynamicSharedMemorySize, GSMEM);
    cudaFuncSetAttribute(gemm_mma<GM_DUAL>,  cudaFuncAttributeMaxDynamicSharedMemorySize, GSMEM);

    split_all<<<dim3(9216, 4), 256>>>(
        caw, wq_h, wq_l, NL * D3 * DM / 4,
        cpw, wp_h, wp_l, NL * DM * DM / 4,
        cfw, wf_h, wf_l, NL * D4 * DM / 4,
        mpw, wm_h, wm_l, NL * DM * D4 / 4);

    embed_kernel<<<BT, 192>>>(idx, wte, wpe, x);

    for (int l = 0; l < NL; l++) {
        size_t oq = (size_t)l * D3 * DM, op = (size_t)l * DM * DM;
        size_t of = (size_t)l * D4 * DM, ow = (size_t)l * D4 * D4, om = (size_t)l * DM * D4;
        ln_kernel<true><<<BT, 256>>>(x, DM, ln1_w + l * DM, ln1_b + l * DM, nullptr, xn_h, xn_l);
        gemm_mma<GM_F32><<<dim3(D3 / 128, BT / 128), 256, GSMEM>>>(
            xn_h, xn_l, wq_h + oq, wq_l + oq, cab + l * D3, qkv, nullptr, nullptr,
            nullptr, nullptr, nullptr, nullptr, D3, DM, DM);
        attn_mma<<<dim3(TT / 64, BB * NHEAD), 128, ATSM>>>(qkv, att_h, att_l);
        // proj: split-K x2
        gemm_mma<GM_PART><<<dim3(DM / 128, BT / 128, 2), 256, GSMEM>>>(
            att_h, att_l, wp_h + op, wp_l + op, cpb + l * DM, part, nullptr, nullptr,
            nullptr, nullptr, nullptr, nullptr, DM, DM / 2, DM);
        addparts<<<(BT * DM / 4 + 255) / 256, 256>>>(x, part, BT * DM / 4);
        ln_kernel<true><<<BT, 256>>>(x, DM, ln2_w + l * DM, ln2_b + l * DM, nullptr, xn_h, xn_l);
        if (l == 0) {
            transpose_all<<<dim3(D4 / 32, D4 / 32, 2 * NL), dim3(32, 8)>>>(
                swW, swV, wW_h, wW_l, wV_h, wV_l);
        }
        gemm_mma<GM_SPLIT><<<dim3(D4 / 128, BT / 128), 256, GSMEM>>>(
            xn_h, xn_l, wf_h + of, wf_l + of, cfb + l * D4, nullptr, h_h, h_l,
            nullptr, nullptr, nullptr, nullptr, D4, DM, DM);
        // swW + swV merged into one launch (z selects weights/bias/output plane)
        gemm_mma<GM_DUAL><<<dim3(D4 / 128, BT / 128, 2), 256, GSMEM>>>(
            h_h, h_l, wW_h + ow, wW_l + ow, swb + l * D4, a, nullptr, nullptr,
            wV_h + ow, wV_l + ow, swc + l * D4, c2f, D4, D4, D4);
        swiglu_split<<<(BT * D4 / 4 + 255) / 256, 256>>>(a, c2f, c2_h, c2_l, BT * D4 / 4);
        // mlp_proj: split-K x2
        gemm_mma<GM_PART><<<dim3(DM / 128, BT / 128, 2), 256, GSMEM>>>(
            c2_h, c2_l, wm_h + om, wm_l + om, mpb + l * DM, part, nullptr, nullptr,
            nullptr, nullptr, nullptr, nullptr, DM, D4 / 2, D4);
        addparts<<<(BT * DM / 4 + 255) / 256, 256>>>(x, part, BT * DM / 4);
    }

    ln_kernel<false><<<BB, 256>>>(x + (size_t)(TT - 1) * DM, (size_t)TT * DM,
                                  lnf_w, lnf_b, xf, nullptr, nullptr);
    sgemm_kernel<<<dim3(VV / 128, 1), 256>>>(xf, lmw, out, BB, VV, DM);
}

// round 16
// speedup vs baseline: 1.1246x; 1.0027x over previous
#include <cuda_runtime.h>
#include <cuda_bf16.h>
#include <math.h>
#include <stdint.h>

#define BB 4
#define TT 1024
#define DM 768
#define NHEAD 12
#define HDIM 64
#define NL 4
#define VV 50304
#define D3 2304
#define D4 3072
#define BT 4096   // B*T

typedef __nv_bfloat16 bf16;

// ---------------- scratch (device globals; no allocation anywhere) ----------------
__device__ float g_x  [BT * DM];
__device__ float g_qkv[BT * D3];
__device__ float g_a  [BT * D4];
__device__ float g_c2f[BT * D4];
__device__ float g_xf [BB * DM];
__device__ float g_part[2 * BT * DM];     // split-K partials
__device__ bf16 g_xn_h [BT * DM],  g_xn_l [BT * DM];
__device__ bf16 g_att_h[BT * DM],  g_att_l[BT * DM];
__device__ bf16 g_h_h  [BT * D4],  g_h_l  [BT * D4];
__device__ bf16 g_c2_h [BT * D4],  g_c2_l [BT * D4];
// pre-split qkv
__device__ bf16 g_q_h[BT * DM], g_q_l[BT * DM];
__device__ bf16 g_k_h[BT * DM], g_k_l[BT * DM];
__device__ bf16 g_v_h[BT * DM], g_v_l[BT * DM];
// split-bf16 weights, all stored [N][K] (K contiguous)
__device__ bf16 g_wq_h[NL * D3 * DM], g_wq_l[NL * D3 * DM];
__device__ bf16 g_wp_h[NL * DM * DM], g_wp_l[NL * DM * DM];
__device__ bf16 g_wf_h[NL * D4 * DM], g_wf_l[NL * D4 * DM];
__device__ bf16 g_wW_h[NL * D4 * D4], g_wW_l[NL * D4 * D4];
__device__ bf16 g_wV_h[NL * D4 * D4], g_wV_l[NL * D4 * D4];
__device__ bf16 g_wm_h[NL * DM * D4], g_wm_l[NL * DM * D4];

// ================= asm helpers (base sm_103 features only) =================
__device__ __forceinline__ uint32_t smem_u32(const void* p) {
    uint32_t a;
    asm("{ .reg .u64 t; cvta.to.shared.u64 t, %1; cvt.u32.u64 %0, t; }" : "=r"(a) : "l"(p));
    return a;
}
__device__ __forceinline__ float fexp2(float x) {
    float r;
    asm("ex2.approx.ftz.f32 %0, %1;" : "=f"(r) : "f"(x));
    return r;
}
#define SWZ(off) ((off) ^ (((off) >> 3) & 0x70))

#define CP16(dst, src) \
    asm volatile("cp.async.cg.shared.global [%0], [%1], 16;" :: "r"(dst), "l"(src) : "memory")
#define CP_COMMIT() asm volatile("cp.async.commit_group;" ::: "memory")
#define CP_WAIT1()  asm volatile("cp.async.wait_group 1;"  ::: "memory")
#define CP_WAIT0()  asm volatile("cp.async.wait_group 0;"  ::: "memory")

#define LDM4(r0, r1, r2, r3, addr) \
    asm volatile("ldmatrix.sync.aligned.m8n8.x4.shared.b16 {%0,%1,%2,%3}, [%4];" \
                 : "=r"(r0), "=r"(r1), "=r"(r2), "=r"(r3) : "r"(addr))

#define LDM4T(r0, r1, r2, r3, addr) \
    asm volatile("ldmatrix.sync.aligned.m8n8.x4.trans.shared.b16 {%0,%1,%2,%3}, [%4];" \
                 : "=r"(r0), "=r"(r1), "=r"(r2), "=r"(r3) : "r"(addr))

#define MMA(D, A, B) \
    asm volatile("mma.sync.aligned.m16n8k16.row.col.f32.bf16.bf16.f32 " \
                 "{%0,%1,%2,%3}, {%4,%5,%6,%7}, {%8,%9}, {%0,%1,%2,%3};" \
                 : "+f"((D)[0]), "+f"((D)[1]), "+f"((D)[2]), "+f"((D)[3]) \
                 : "r"((A)[0]), "r"((A)[1]), "r"((A)[2]), "r"((A)[3]), \
                   "r"((B)[0]), "r"((B)[1]))

__device__ __forceinline__ void split2_store(bf16* H, bf16* L, size_t off, float v0, float v1) {
    bf16 h0 = __float2bfloat16(v0), h1 = __float2bfloat16(v1);
    bf16 l0 = __float2bfloat16(v0 - __bfloat162float(h0));
    bf16 l1 = __float2bfloat16(v1 - __bfloat162float(h1));
    *(__nv_bfloat162*)(H + off) = __halves2bfloat162(h0, h1);
    *(__nv_bfloat162*)(L + off) = __halves2bfloat162(l0, l1);
}

__device__ __forceinline__ void splitpack(float x, float y, uint32_t& hi, uint32_t& lo) {
    bf16 xh = __float2bfloat16(x), yh = __float2bfloat16(y);
    bf16 xl = __float2bfloat16(x - __bfloat162float(xh));
    bf16 yl = __float2bfloat16(y - __bfloat162float(yh));
    hi = (uint32_t)__bfloat16_as_ushort(xh) | ((uint32_t)__bfloat16_as_ushort(yh) << 16);
    lo = (uint32_t)__bfloat16_as_ushort(xl) | ((uint32_t)__bfloat16_as_ushort(yl) << 16);
}

// ---------------- weight conversion ----------------
__global__ void split_all(const float* __restrict__ s0, bf16* h0, bf16* l0, int n0,
                          const float* __restrict__ s1, bf16* h1, bf16* l1, int n1,
                          const float* __restrict__ s2, bf16* h2, bf16* l2, int n2,
                          const float* __restrict__ s3, bf16* h3, bf16* l3, int n3) {
    const float* s; bf16 *h, *l; int n;
    switch (blockIdx.y) {
        case 0: s = s0; h = h0; l = l0; n = n0; break;
        case 1: s = s1; h = h1; l = l1; n = n1; break;
        case 2: s = s2; h = h2; l = l2; n = n2; break;
        default:s = s3; h = h3; l = l3; n = n3; break;
    }
    int i = blockIdx.x * blockDim.x + threadIdx.x;
    if (i >= n) return;
    float4 v = ((const float4*)s)[i];
    split2_store(h, l, (size_t)i * 4,     v.x, v.y);
    split2_store(h, l, (size_t)i * 4 + 2, v.z, v.w);
}

__global__ void transpose_all(const float* __restrict__ W, const float* __restrict__ V,
                              bf16* __restrict__ Wh, bf16* __restrict__ Wl,
                              bf16* __restrict__ Vh, bf16* __restrict__ Vl) {
    __shared__ float t[32][33];
    int z = blockIdx.z;
    int l = (z < NL) ? z : z - NL;
    const float* s = ((z < NL) ? W : V) + (size_t)l * D4 * D4;
    bf16* H = ((z < NL) ? Wh : Vh) + (size_t)l * D4 * D4;
    bf16* L = ((z < NL) ? Wl : Vl) + (size_t)l * D4 * D4;
    int n0 = blockIdx.x * 32, k0 = blockIdx.y * 32;
    int cx = threadIdx.x;
    #pragma unroll
    for (int r = threadIdx.y; r < 32; r += 8)
        t[r][cx] = s[(size_t)(k0 + r) * D4 + n0 + cx];
    __syncthreads();
    #pragma unroll
    for (int r = threadIdx.y; r < 32; r += 8) {
        float v = t[cx][r];
        size_t off = (size_t)(n0 + r) * D4 + k0 + cx;
        bf16 h = __float2bfloat16(v);
        H[off] = h;
        L[off] = __float2bfloat16(v - __bfloat162float(h));
    }
}

// ---------------- qkv fp32 -> pre-split q/k/v bf16 ----------------
__global__ void qkv_split(const float* __restrict__ qkv,
                          bf16* __restrict__ qh, bf16* __restrict__ ql,
                          bf16* __restrict__ kh, bf16* __restrict__ kl,
                          bf16* __restrict__ vh, bf16* __restrict__ vl) {
    int i = blockIdx.x * blockDim.x + threadIdx.x;   // float4 index, BT*D3/4 total
    const int per_row = D3 / 4;
    int bt = i / per_row, c4 = (i % per_row) * 4;
    float4 v = *(const float4*)&qkv[(size_t)bt * D3 + c4];
    bf16 *H, *L; int cc;
    if (c4 < DM)          { H = qh; L = ql; cc = c4; }
    else if (c4 < 2 * DM) { H = kh; L = kl; cc = c4 - DM; }
    else                  { H = vh; L = vl; cc = c4 - 2 * DM; }
    size_t off = (size_t)bt * DM + cc;
    split2_store(H, L, off,     v.x, v.y);
    split2_store(H, L, off + 2, v.z, v.w);
}

// ---------------- embedding ----------------
__global__ void embed_kernel(const int* __restrict__ idx, const float* __restrict__ wte,
                             const float* __restrict__ wpe, float* __restrict__ x) {
    int bt = blockIdx.x;
    int t  = bt & (TT - 1);
    int tok = idx[bt];
    int c = threadIdx.x * 4;
    float4 a = *(const float4*)&wte[(size_t)tok * DM + c];
    float4 p = *(const float4*)&wpe[(size_t)t   * DM + c];
    a.x += p.x; a.y += p.y; a.z += p.z; a.w += p.w;
    *(float4*)&x[(size_t)bt * DM + c] = a;
}

// ---------------- split-K partial reduce: x += p0 + p1 ----------------
__global__ void addparts(float* __restrict__ x, const float* __restrict__ p, int n4) {
    int i = blockIdx.x * blockDim.x + threadIdx.x;
    if (i >= n4) return;
    float4 xv = ((const float4*)x)[i];
    float4 a = ((const float4*)p)[i];
    float4 b = ((const float4*)(p + (size_t)BT * DM))[i];
    xv.x += a.x + b.x; xv.y += a.y + b.y; xv.z += a.z + b.z; xv.w += a.w + b.w;
    ((float4*)x)[i] = xv;
}

// ---------------- elementwise swiglu + split ----------------
__global__ void swiglu_split(const float* __restrict__ a, const float* __restrict__ c2f,
                             bf16* __restrict__ H, bf16* __restrict__ L, int n4) {
    int i = blockIdx.x * blockDim.x + threadIdx.x;
    if (i >= n4) return;
    float4 g = ((const float4*)a)[i];
    float4 v = ((const float4*)c2f)[i];
    float o0 = g.x / (1.f + __expf(-g.x)) * v.x;
    float o1 = g.y / (1.f + __expf(-g.y)) * v.y;
    float o2 = g.z / (1.f + __expf(-g.z)) * v.z;
    float o3 = g.w / (1.f + __expf(-g.w)) * v.w;
    split2_store(H, L, (size_t)i * 4,     o0, o1);
    split2_store(H, L, (size_t)i * 4 + 2, o2, o3);
}

// ---------------- layernorm ----------------
template <bool SPLIT>
__global__ __launch_bounds__(256)
void ln_kernel(const float* __restrict__ x, size_t rstride,
               const float* __restrict__ w, const float* __restrict__ b,
               float* __restrict__ yf, bf16* __restrict__ yh, bf16* __restrict__ yl) {
    const float* xr = x + (size_t)blockIdx.x * rstride;
    int tid = threadIdx.x;

    float v0 = xr[tid], v1 = xr[tid + 256], v2 = xr[tid + 512];
    float s  = v0 + v1 + v2;
    float s2 = v0 * v0 + v1 * v1 + v2 * v2;
    #pragma unroll
    for (int off = 16; off; off >>= 1) {
        s  += __shfl_xor_sync(0xffffffffu, s,  off);
        s2 += __shfl_xor_sync(0xffffffffu, s2, off);
    }
    __shared__ float sh_s[8], sh_s2[8];
    int wid = tid >> 5, lane = tid & 31;
    if (lane == 0) { sh_s[wid] = s; sh_s2[wid] = s2; }
    __syncthreads();
    float tot = 0.f, tot2 = 0.f;
    #pragma unroll
    for (int i = 0; i < 8; i++) { tot += sh_s[i]; tot2 += sh_s2[i]; }
    const float inv = 1.0f / (float)DM;
    float mean = tot * inv;
    float var  = tot2 * inv - mean * mean;
    float rstd = rsqrtf(var + 1e-5f);

    size_t base = (size_t)blockIdx.x * DM;
    float o0 = (v0 - mean) * rstd * w[tid]       + b[tid];
    float o1 = (v1 - mean) * rstd * w[tid + 256] + b[tid + 256];
    float o2 = (v2 - mean) * rstd * w[tid + 512] + b[tid + 512];
    if (SPLIT) {
        bf16 h0 = __float2bfloat16(o0);
        yh[base + tid] = h0;       yl[base + tid]       = __float2bfloat16(o0 - __bfloat162float(h0));
        bf16 h1 = __float2bfloat16(o1);
        yh[base + tid + 256] = h1; yl[base + tid + 256] = __float2bfloat16(o1 - __bfloat162float(h1));
        bf16 h2 = __float2bfloat16(o2);
        yh[base + tid + 512] = h2; yl[base + tid + 512] = __float2bfloat16(o2 - __bfloat162float(h2));
    } else {
        yf[base + tid]       = o0;
        yf[base + tid + 256] = o1;
        yf[base + tid + 512] = o2;
    }
}

// ================= mma.sync split-bf16 GEMM =================
#define GM_F32    0
#define GM_RES    1
#define GM_SPLIT  2
#define GM_PART   3
#define GM_DUAL   4

#define GSTAGE 65536
#define GSMEM  (3 * GSTAGE + 1024)

struct Frags {
    uint32_t aH[2][4], aL[2][4], bH[8][2], bL[8][2];
};

template <int MODE>
__global__ __launch_bounds__(256, 1)
void gemm_mma(const bf16* __restrict__ Ah, const bf16* __restrict__ Al,
              const bf16* __restrict__ Bh, const bf16* __restrict__ Bl,
              const float* __restrict__ bias,
              float* __restrict__ Cf, bf16* __restrict__ Ch, bf16* __restrict__ Cl,
              const bf16* __restrict__ B2h, const bf16* __restrict__ B2l,
              const float* __restrict__ bias2, float* __restrict__ Cf2,
              int N, int K, int lda) {
    extern __shared__ char dyn[];
    uint32_t base = (smem_u32(dyn) + 1023) & ~1023u;

    const int tid = threadIdx.x;
    const int bm = blockIdx.y * 128, bn = blockIdx.x * 128;
    const int koff = (MODE == GM_PART) ? blockIdx.z * K : 0;
    const int lane = tid & 31, wid = tid >> 5;
    const int wm = wid & 3, wn = wid >> 2;

    const bf16* Bh_ = Bh;
    const bf16* Bl_ = Bl;
    const float* bias_ = bias;
    float* Cf_ = Cf;
    if (MODE == GM_DUAL && blockIdx.z) { Bh_ = B2h; Bl_ = B2l; bias_ = bias2; Cf_ = Cf2; }

    const int lr = ((lane >> 3) & 1) * 8 + (lane & 7);
    const int lk = lane >> 4;

    float d[2][8][4];
    #pragma unroll
    for (int i = 0; i < 2; i++)
        #pragma unroll
        for (int j = 0; j < 8; j++)
            #pragma unroll
            for (int q = 0; q < 4; q++) d[i][j][q] = 0.f;

    const int nkt = K >> 6;

    auto load_stage = [&](int kt, int sb) {
        uint32_t st = base + sb * GSTAGE;
        int k0 = koff + (kt << 6);
        #pragma unroll
        for (int i = 0; i < 4; i++) {
            int row = (tid >> 3) + i * 32;
            int seg = tid & 7;
            uint32_t soff = SWZ(row * 128 + seg * 16);
            size_t ga = (size_t)(bm + row) * lda + k0 + seg * 8;
            size_t gb = (size_t)(bn + row) * lda + k0 + seg * 8;
            CP16(st + soff,         Ah + ga);
            CP16(st + 16384 + soff, Al + ga);
            CP16(st + 32768 + soff, Bh_ + gb);
            CP16(st + 49152 + soff, Bl_ + gb);
        }
    };

    auto load_frags = [&](uint32_t st, int ks, Frags& f) {
        #pragma unroll
        for (int am = 0; am < 2; am++) {
            int row = wm * 32 + am * 16 + lr;
            uint32_t off = SWZ(row * 128 + (ks * 2 + lk) * 16);
            LDM4(f.aH[am][0], f.aH[am][1], f.aH[am][2], f.aH[am][3], st + off);
            LDM4(f.aL[am][0], f.aL[am][1], f.aL[am][2], f.aL[am][3], st + 16384 + off);
        }
        #pragma unroll
        for (int nb = 0; nb < 4; nb++) {
            int row = wn * 64 + nb * 16 + lr;
            uint32_t off = SWZ(row * 128 + (ks * 2 + lk) * 16);
            uint32_t t0, t1, t2, t3;
            LDM4(t0, t1, t2, t3, st + 32768 + off);
            f.bH[2*nb][0] = t0; f.bH[2*nb][1] = t2; f.bH[2*nb+1][0] = t1; f.bH[2*nb+1][1] = t3;
            LDM4(t0, t1, t2, t3, st + 49152 + off);
            f.bL[2*nb][0] = t0; f.bL[2*nb][1] = t2; f.bL[2*nb+1][0] = t1; f.bL[2*nb+1][1] = t3;
        }
    };
    auto do_mma = [&](Frags& f) {
        #pragma unroll
        for (int am = 0; am < 2; am++)
            #pragma unroll
            for (int an = 0; an < 8; an++) {
                MMA(d[am][an], f.aH[am], f.bH[an]);
                MMA(d[am][an], f.aH[am], f.bL[an]);
                MMA(d[am][an], f.aL[am], f.bH[an]);
            }
    };

    load_stage(0, 0); CP_COMMIT();
    load_stage(1, 1); CP_COMMIT();

    Frags fr[2];
    for (int kt = 0; kt < nkt; kt++) {
        CP_WAIT1();
        __syncthreads();
        if (kt + 2 < nkt) load_stage(kt + 2, (kt + 2) % 3);
        CP_COMMIT();

        uint32_t st = base + (kt % 3) * GSTAGE;
        load_frags(st, 0, fr[0]);
        #pragma unroll
        for (int ks = 0; ks < 4; ks++) {
            if (ks < 3) load_frags(st, ks + 1, fr[(ks + 1) & 1]);
            do_mma(fr[ks & 1]);
        }
    }

    const int g = lane >> 2, tq = lane & 3;
    #pragma unroll
    for (int am = 0; am < 2; am++)
        #pragma unroll
        for (int an = 0; an < 8; an++) {
            int r0 = bm + wm * 32 + am * 16 + g;
            int c  = bn + wn * 64 + an * 8 + tq * 2;
            #pragma unroll
            for (int half = 0; half < 2; half++) {
                int row = r0 + half * 8;
                float v0 = d[am][an][half * 2];
                float v1 = d[am][an][half * 2 + 1];
                if (MODE != GM_PART || blockIdx.z == 0) { v0 += bias_[c]; v1 += bias_[c + 1]; }
                size_t off = (size_t)row * N + c;
                if (MODE == GM_F32 || MODE == GM_DUAL) {
                    *(float2*)(Cf_ + off) = make_float2(v0, v1);
                } else if (MODE == GM_RES) {
                    float2 o = *(const float2*)(Cf_ + off);
                    *(float2*)(Cf_ + off) = make_float2(v0 + o.x, v1 + o.y);
                } else if (MODE == GM_SPLIT) {
                    split2_store(Ch, Cl, off, v0, v1);
                } else {  // GM_PART
                    *(float2*)(Cf_ + (size_t)blockIdx.z * BT * DM + off) = make_float2(v0, v1);
                }
            }
        }
}

// ---------------- SIMT sgemm (lm_head only, M=4) ----------------
__global__ __launch_bounds__(256)
void sgemm_kernel(const float* __restrict__ A, const float* __restrict__ B,
                  float* __restrict__ C, int M, int N, int K) {
    __shared__ float As[8 * 128];
    __shared__ float Bs[8 * 128];

    const int tid = threadIdx.x;
    const int tx = tid & 15, ty = tid >> 4;
    const int bm = blockIdx.y * 128, bn = blockIdx.x * 128;

    float acc[8][8];
    #pragma unroll
    for (int i = 0; i < 8; i++)
        #pragma unroll
        for (int j = 0; j < 8; j++) acc[i][j] = 0.f;

    const int arow = tid >> 1;
    const int acol = (tid & 1) * 4;

    for (int k0 = 0; k0 < K; k0 += 8) {
        float4 av = make_float4(0.f, 0.f, 0.f, 0.f);
        if (bm + arow < M)
            av = *(const float4*)&A[(size_t)(bm + arow) * K + k0 + acol];
        As[(acol + 0) * 128 + arow] = av.x;
        As[(acol + 1) * 128 + arow] = av.y;
        As[(acol + 2) * 128 + arow] = av.z;
        As[(acol + 3) * 128 + arow] = av.w;
        float4 bv = *(const float4*)&B[(size_t)(bn + arow) * K + k0 + acol];
        Bs[(acol + 0) * 128 + arow] = bv.x;
        Bs[(acol + 1) * 128 + arow] = bv.y;
        Bs[(acol + 2) * 128 + arow] = bv.z;
        Bs[(acol + 3) * 128 + arow] = bv.w;
        __syncthreads();

        #pragma unroll
        for (int kk = 0; kk < 8; kk++) {
            float a[8], b[8];
            *(float4*)&a[0] = *(const float4*)&As[kk * 128 + ty * 8];
            *(float4*)&a[4] = *(const float4*)&As[kk * 128 + ty * 8 + 4];
            *(float4*)&b[0] = *(const float4*)&Bs[kk * 128 + tx * 8];
            *(float4*)&b[4] = *(const float4*)&Bs[kk * 128 + tx * 8 + 4];
            #pragma unroll
            for (int i = 0; i < 8; i++)
                #pragma unroll
                for (int j = 0; j < 8; j++)
                    acc[i][j] = fmaf(a[i], b[j], acc[i][j]);
        }
        __syncthreads();
    }

    #pragma unroll
    for (int i = 0; i < 8; i++) {
        int row = bm + ty * 8 + i;
        if (row >= M) continue;
        #pragma unroll
        for (int j = 0; j < 8; j++)
            C[(size_t)row * N + bn + tx * 8 + j] = acc[i][j];
    }
}

// ================= HMMA flash attention (pre-split q/k/v, zero in-loop convert) =====
#define ATSM (6 * 8192)

__global__ __launch_bounds__(128)
void attn_mma(const bf16* __restrict__ qh, const bf16* __restrict__ ql,
              const bf16* __restrict__ kh, const bf16* __restrict__ kl,
              const bf16* __restrict__ vh, const bf16* __restrict__ vl,
              bf16* __restrict__ oh, bf16* __restrict__ ol) {
    extern __shared__ char smn[];
    const uint32_t uq_h = smem_u32(smn);
    const uint32_t uq_l = uq_h + 8192;
    const uint32_t uk_h = uq_h + 16384, uk_l = uq_h + 24576;
    const uint32_t uv_h = uq_h + 32768, uv_l = uq_h + 40960;

    const int tid = threadIdx.x;
    const int lane = tid & 31, w = tid >> 5;
    const int qi = blockIdx.x;
    const int b = blockIdx.y / NHEAD, h = blockIdx.y % NHEAD;
    const int lr = ((lane >> 3) & 1) * 8 + (lane & 7);
    const int lk = lane >> 4;
    const int g = lane >> 2, tq = lane & 3;
    const int gi = lane >> 3;
    const int pv_row = ((gi >> 1) & 1) * 8 + (lane & 7);
    const int pv_col = (gi & 1) * 8;

    const float SC = 0.18033688011112042f;   // 0.125 * log2(e)

    // ---- Q tile via cp.async (pre-split) ----
    #pragma unroll
    for (int it = 0; it < 4; it++) {
        int i = tid + it * 128;
        int row = i >> 3, seg = i & 7;
        uint32_t off = SWZ(row * 128 + seg * 16);
        size_t gq = (size_t)(b * TT + qi * 64 + row) * DM + h * HDIM + seg * 8;
        CP16(uq_h + off, qh + gq);
        CP16(uq_l + off, ql + gq);
    }
    CP_COMMIT();
    CP_WAIT0();
    __syncthreads();

    uint32_t qAh[4][4], qAl[4][4];
    #pragma unroll
    for (int kk = 0; kk < 4; kk++) {
        uint32_t off = SWZ((w * 16 + lr) * 128 + (kk * 2 + lk) * 16);
        LDM4(qAh[kk][0], qAh[kk][1], qAh[kk][2], qAh[kk][3], uq_h + off);
        LDM4(qAl[kk][0], qAl[kk][1], qAl[kk][2], qAl[kk][3], uq_l + off);
    }

    float m0 = -1e30f, m1 = -1e30f, l0 = 0.f, l1 = 0.f;
    float o[8][4];
    #pragma unroll
    for (int j = 0; j < 8; j++)
        #pragma unroll
        for (int q = 0; q < 4; q++) o[j][q] = 0.f;

    const int rg0 = qi * 64 + w * 16 + g;

    for (int kt = 0; kt <= qi; kt++) {
        __syncthreads();
        // ---- K/V tiles via cp.async, no conversion ----
        #pragma unroll
        for (int it = 0; it < 4; it++) {
            int i = tid + it * 128;
            int row = i >> 3, seg = i & 7;
            uint32_t off = SWZ(row * 128 + seg * 16);
            size_t gg = (size_t)(b * TT + kt * 64 + row) * DM + h * HDIM + seg * 8;
            CP16(uk_h + off, kh + gg);
            CP16(uk_l + off, kl + gg);
            CP16(uv_h + off, vh + gg);
            CP16(uv_l + off, vl + gg);
        }
        CP_COMMIT();
        CP_WAIT0();
        __syncthreads();

        float s[8][4];
        #pragma unroll
        for (int j = 0; j < 8; j++)
            #pragma unroll
            for (int q = 0; q < 4; q++) s[j][q] = 0.f;

        #pragma unroll
        for (int kk = 0; kk < 4; kk++) {
            uint32_t th[4][4], tl[4][4];
            #pragma unroll
            for (int nb = 0; nb < 4; nb++) {
                uint32_t off = SWZ((nb * 16 + lr) * 128 + (kk * 2 + lk) * 16);
                LDM4(th[nb][0], th[nb][1], th[nb][2], th[nb][3], uk_h + off);
                LDM4(tl[nb][0], tl[nb][1], tl[nb][2], tl[nb][3], uk_l + off);
            }
            #pragma unroll
            for (int nb = 0; nb < 4; nb++) {
                uint32_t B0h[2] = {th[nb][0], th[nb][2]};
                uint32_t B1h[2] = {th[nb][1], th[nb][3]};
                uint32_t B0l[2] = {tl[nb][0], tl[nb][2]};
                uint32_t B1l[2] = {tl[nb][1], tl[nb][3]};
                MMA(s[2*nb],   qAh[kk], B0h);
                MMA(s[2*nb],   qAh[kk], B0l);
                MMA(s[2*nb],   qAl[kk], B0h);
                MMA(s[2*nb+1], qAh[kk], B1h);
                MMA(s[2*nb+1], qAh[kk], B1l);
                MMA(s[2*nb+1], qAl[kk], B1h);
            }
        }

        #pragma unroll
        for (int j = 0; j < 8; j++) {
            s[j][0] *= SC; s[j][1] *= SC; s[j][2] *= SC; s[j][3] *= SC;
        }
        if (kt == qi) {
            #pragma unroll
            for (int j = 0; j < 8; j++) {
                int col = kt * 64 + j * 8 + tq * 2;
                if (col     > rg0)     s[j][0] = -1e30f;
                if (col + 1 > rg0)     s[j][1] = -1e30f;
                if (col     > rg0 + 8) s[j][2] = -1e30f;
                if (col + 1 > rg0 + 8) s[j][3] = -1e30f;
            }
        }

        float mt0 = -1e30f, mt1 = -1e30f;
        #pragma unroll
        for (int j = 0; j < 8; j++) {
            mt0 = fmaxf(mt0, fmaxf(s[j][0], s[j][1]));
            mt1 = fmaxf(mt1, fmaxf(s[j][2], s[j][3]));
        }
        mt0 = fmaxf(mt0, __shfl_xor_sync(0xffffffffu, mt0, 1));
        mt0 = fmaxf(mt0, __shfl_xor_sync(0xffffffffu, mt0, 2));
        mt1 = fmaxf(mt1, __shfl_xor_sync(0xffffffffu, mt1, 1));
        mt1 = fmaxf(mt1, __shfl_xor_sync(0xffffffffu, mt1, 2));
        float mn0 = fmaxf(m0, mt0), mn1 = fmaxf(m1, mt1);
        float a0 = fexp2(m0 - mn0), a1 = fexp2(m1 - mn1);
        m0 = mn0; m1 = mn1;

        float sum0 = 0.f, sum1 = 0.f;
        #pragma unroll
        for (int j = 0; j < 8; j++) {
            s[j][0] = fexp2(s[j][0] - mn0);
            s[j][1] = fexp2(s[j][1] - mn0);
            s[j][2] = fexp2(s[j][2] - mn1);
            s[j][3] = fexp2(s[j][3] - mn1);
            sum0 += s[j][0] + s[j][1];
            sum1 += s[j][2] + s[j][3];
        }
        sum0 += __shfl_xor_sync(0xffffffffu, sum0, 1);
        sum0 += __shfl_xor_sync(0xffffffffu, sum0, 2);
        sum1 += __shfl_xor_sync(0xffffffffu, sum1, 1);
        sum1 += __shfl_xor_sync(0xffffffffu, sum1, 2);
        l0 = l0 * a0 + sum0;
        l1 = l1 * a1 + sum1;
        #pragma unroll
        for (int j = 0; j < 8; j++) {
            o[j][0] *= a0; o[j][1] *= a0; o[j][2] *= a1; o[j][3] *= a1;
        }

        uint32_t pH[4][4], pL[4][4];
        #pragma unroll
        for (int kk = 0; kk < 4; kk++) {
            splitpack(s[2*kk][0],   s[2*kk][1],   pH[kk][0], pL[kk][0]);
            splitpack(s[2*kk][2],   s[2*kk][3],   pH[kk][1], pL[kk][1]);
            splitpack(s[2*kk+1][0], s[2*kk+1][1], pH[kk][2], pL[kk][2]);
            splitpack(s[2*kk+1][2], s[2*kk+1][3], pH[kk][3], pL[kk][3]);
        }

        #pragma unroll
        for (int kk = 0; kk < 4; kk++) {
            uint32_t th[4][4], tl[4][4];
            #pragma unroll
            for (int nb = 0; nb < 4; nb++) {
                uint32_t off = SWZ((kk * 16 + pv_row) * 128 + (nb * 16 + pv_col) * 2);
                LDM4T(th[nb][0], th[nb][1], th[nb][2], th[nb][3], uv_h + off);
                LDM4T(tl[nb][0], tl[nb][1], tl[nb][2], tl[nb][3], uv_l + off);
            }
            #pragma unroll
            for (int nb = 0; nb < 4; nb++) {
                uint32_t B0h[2] = {th[nb][0], th[nb][2]};
                uint32_t B1h[2] = {th[nb][1], th[nb][3]};
                uint32_t B0l[2] = {tl[nb][0], tl[nb][2]};
                uint32_t B1l[2] = {tl[nb][1], tl[nb][3]};
                MMA(o[2*nb],   pH[kk], B0h);
                MMA(o[2*nb],   pH[kk], B0l);
                MMA(o[2*nb],   pL[kk], B0h);
                MMA(o[2*nb+1], pH[kk], B1h);
                MMA(o[2*nb+1], pH[kk], B1l);
                MMA(o[2*nb+1], pL[kk], B1h);
            }
        }
    }

    float i0 = 1.f / l0, i1 = 1.f / l1;
    size_t r0 = (size_t)(b * TT + qi * 64 + w * 16 + g);
    #pragma unroll
    for (int j = 0; j < 8; j++) {
        int col = h * HDIM + j * 8 + tq * 2;
        split2_store(oh, ol, r0 * DM + col,       o[j][0] * i0, o[j][1] * i0);
        split2_store(oh, ol, (r0 + 8) * DM + col, o[j][2] * i1, o[j][3] * i1);
    }
}

// ---------------- launcher ----------------
extern "C" void kernel_launch(void* const* d_in, const int* in_sizes, int n_in,
                              void* d_out, int out_size) {
    const int*   idx    = (const int*)  d_in[0];
    const float* wte    = (const float*)d_in[1];
    const float* wpe    = (const float*)d_in[2];
    const float* ln1_w  = (const float*)d_in[3];
    const float* ln1_b  = (const float*)d_in[4];
    const float* caw    = (const float*)d_in[5];
    const float* cab    = (const float*)d_in[6];
    const float* cpw    = (const float*)d_in[7];
    const float* cpb    = (const float*)d_in[8];
    const float* ln2_w  = (const float*)d_in[9];
    const float* ln2_b  = (const float*)d_in[10];
    const float* cfw    = (const float*)d_in[11];
    const float* cfb    = (const float*)d_in[12];
    const float* swW    = (const float*)d_in[13];
    const float* swV    = (const float*)d_in[14];
    const float* swb    = (const float*)d_in[15];
    const float* swc    = (const float*)d_in[16];
    const float* mpw    = (const float*)d_in[17];
    const float* mpb    = (const float*)d_in[18];
    const float* lnf_w  = (const float*)d_in[19];
    const float* lnf_b  = (const float*)d_in[20];
    const float* lmw    = (const float*)d_in[21];
    float* out = (float*)d_out;

    float *x, *qkv, *a, *c2f, *xf, *part;
    bf16 *xn_h, *xn_l, *att_h, *att_l, *h_h, *h_l, *c2_h, *c2_l;
    bf16 *q_h, *q_l, *k_h, *k_l, *v_h, *v_l;
    bf16 *wq_h, *wq_l, *wp_h, *wp_l, *wf_h, *wf_l, *wW_h, *wW_l, *wV_h, *wV_l, *wm_h, *wm_l;
    cudaGetSymbolAddress((void**)&x,    g_x);
    cudaGetSymbolAddress((void**)&qkv,  g_qkv);
    cudaGetSymbolAddress((void**)&a,    g_a);
    cudaGetSymbolAddress((void**)&c2f,  g_c2f);
    cudaGetSymbolAddress((void**)&xf,   g_xf);
    cudaGetSymbolAddress((void**)&part, g_part);
    cudaGetSymbolAddress((void**)&xn_h, g_xn_h);  cudaGetSymbolAddress((void**)&xn_l, g_xn_l);
    cudaGetSymbolAddress((void**)&att_h,g_att_h); cudaGetSymbolAddress((void**)&att_l,g_att_l);
    cudaGetSymbolAddress((void**)&h_h,  g_h_h);   cudaGetSymbolAddress((void**)&h_l,  g_h_l);
    cudaGetSymbolAddress((void**)&c2_h, g_c2_h);  cudaGetSymbolAddress((void**)&c2_l, g_c2_l);
    cudaGetSymbolAddress((void**)&q_h,  g_q_h);   cudaGetSymbolAddress((void**)&q_l,  g_q_l);
    cudaGetSymbolAddress((void**)&k_h,  g_k_h);   cudaGetSymbolAddress((void**)&k_l,  g_k_l);
    cudaGetSymbolAddress((void**)&v_h,  g_v_h);   cudaGetSymbolAddress((void**)&v_l,  g_v_l);
    cudaGetSymbolAddress((void**)&wq_h, g_wq_h);  cudaGetSymbolAddress((void**)&wq_l, g_wq_l);
    cudaGetSymbolAddress((void**)&wp_h, g_wp_h);  cudaGetSymbolAddress((void**)&wp_l, g_wp_l);
    cudaGetSymbolAddress((void**)&wf_h, g_wf_h);  cudaGetSymbolAddress((void**)&wf_l, g_wf_l);
    cudaGetSymbolAddress((void**)&wW_h, g_wW_h);  cudaGetSymbolAddress((void**)&wW_l, g_wW_l);
    cudaGetSymbolAddress((void**)&wV_h, g_wV_h);  cudaGetSymbolAddress((void**)&wV_l, g_wV_l);
    cudaGetSymbolAddress((void**)&wm_h, g_wm_h);  cudaGetSymbolAddress((void**)&wm_l, g_wm_l);

    cudaFuncSetAttribute(attn_mma, cudaFuncAttributeMaxDynamicSharedMemorySize, ATSM);
    cudaFuncSetAttribute(gemm_mma<GM_F32>,   cudaFuncAttributeMaxDynamicSharedMemorySize, GSMEM);
    cudaFuncSetAttribute(gemm_mma<GM_RES>,   cudaFuncAttributeMaxDynamicSharedMemorySize, GSMEM);
    cudaFuncSetAttribute(gemm_mma<GM_SPLIT>, cudaFuncAttributeMaxDynamicSharedMemorySize, GSMEM);
    cudaFuncSetAttribute(gemm_mma<GM_PART>,  cudaFuncAttributeMaxDynamicSharedMemorySize, GSMEM);
    cudaFuncSetAttribute(gemm_mma<GM_DUAL>,  cudaFuncAttributeMaxDynamicSharedMemorySize, GSMEM);

    split_all<<<dim3(9216, 4), 256>>>(
        caw, wq_h, wq_l, NL * D3 * DM / 4,
        cpw, wp_h, wp_l, NL * DM * DM / 4,
        cfw, wf_h, wf_l, NL * D4 * DM / 4,
        mpw, wm_h, wm_l, NL * DM * D4 / 4);

    embed_kernel<<<BT, 192>>>(idx, wte, wpe, x);

    for (int l = 0; l < NL; l++) {
        size_t oq = (size_t)l * D3 * DM, op = (size_t)l * DM * DM;
        size_t of = (size_t)l * D4 * DM, ow = (size_t)l * D4 * D4, om = (size_t)l * DM * D4;
        ln_kernel<true><<<BT, 256>>>(x, DM, ln1_w + l * DM, ln1_b + l * DM, nullptr, xn_h, xn_l);
        gemm_mma<GM_F32><<<dim3(D3 / 128, BT / 128), 256, GSMEM>>>(
            xn_h, xn_l, wq_h + oq, wq_l + oq, cab + l * D3, qkv, nullptr, nullptr,
            nullptr, nullptr, nullptr, nullptr, D3, DM, DM);
        qkv_split<<<BT * D3 / 4 / 256, 256>>>(qkv, q_h, q_l, k_h, k_l, v_h, v_l);
        attn_mma<<<dim3(TT / 64, BB * NHEAD), 128, ATSM>>>(
            q_h, q_l, k_h, k_l, v_h, v_l, att_h, att_l);
        // proj: split-K x2
        gemm_mma<GM_PART><<<dim3(DM / 128, BT / 128, 2), 256, GSMEM>>>(
            att_h, att_l, wp_h + op, wp_l + op, cpb + l * DM, part, nullptr, nullptr,
            nullptr, nullptr, nullptr, nullptr, DM, DM / 2, DM);
        addparts<<<(BT * DM / 4 + 255) / 256, 256>>>(x, part, BT * DM / 4);
        ln_kernel<true><<<BT, 256>>>(x, DM, ln2_w + l * DM, ln2_b + l * DM, nullptr, xn_h, xn_l);
        if (l == 0) {
            transpose_all<<<dim3(D4 / 32, D4 / 32, 2 * NL), dim3(32, 8)>>>(
                swW, swV, wW_h, wW_l, wV_h, wV_l);
        }
        gemm_mma<GM_SPLIT><<<dim3(D4 / 128, BT / 128), 256, GSMEM>>>(
            xn_h, xn_l, wf_h + of, wf_l + of, cfb + l * D4, nullptr, h_h, h_l,
            nullptr, nullptr, nullptr, nullptr, D4, DM, DM);
        gemm_mma<GM_DUAL><<<dim3(D4 / 128, BT / 128, 2), 256, GSMEM>>>(
            h_h, h_l, wW_h + ow, wW_l + ow, swb + l * D4, a, nullptr, nullptr,
            wV_h + ow, wV_l + ow, swc + l * D4, c2f, D4, D4, D4);
        swiglu_split<<<(BT * D4 / 4 + 255) / 256, 256>>>(a, c2f, c2_h, c2_l, BT * D4 / 4);
        // mlp_proj: split-K x2
        gemm_mma<GM_PART><<<dim3(DM / 128, BT / 128, 2), 256, GSMEM>>>(
            c2_h, c2_l, wm_h + om, wm_l + om, mpb + l * DM, part, nullptr, nullptr,
            nullptr, nullptr, nullptr, nullptr, DM, D4 / 2, D4);
        addparts<<<(BT * DM / 4 + 255) / 256, 256>>>(x, part, BT * DM / 4);
    }

    ln_kernel<false><<<BB, 256>>>(x + (size_t)(TT - 1) * DM, (size_t)TT * DM,
                                  lnf_w, lnf_b, xf, nullptr, nullptr);
    sgemm_kernel<<<dim3(VV / 128, 1), 256>>>(xf, lmw, out, BB, VV, DM);
}

// round 17
// speedup vs baseline: 1.1362x; 1.0103x over previous
#include <cuda_runtime.h>
#include <cuda_bf16.h>
#include <math.h>
#include <stdint.h>

#define BB 4
#define TT 1024
#define DM 768
#define NHEAD 12
#define HDIM 64
#define NL 4
#define VV 50304
#define D3 2304
#define D4 3072
#define BT 4096   // B*T

typedef __nv_bfloat16 bf16;

// ---------------- scratch (device globals; no allocation anywhere) ----------------
__device__ float g_x  [BT * DM];
__device__ float g_qkv[BT * D3];
__device__ float g_a  [BT * D4];
__device__ float g_c2f[BT * D4];
__device__ float g_xf [BB * DM];
__device__ float g_part[2 * BT * DM];     // split-K partials
__device__ bf16 g_xn_h [BT * DM],  g_xn_l [BT * DM];
__device__ bf16 g_att_h[BT * DM],  g_att_l[BT * DM];
__device__ bf16 g_h_h  [BT * D4],  g_h_l  [BT * D4];
__device__ bf16 g_c2_h [BT * D4],  g_c2_l [BT * D4];
// pre-split qkv
__device__ bf16 g_q_h[BT * DM], g_q_l[BT * DM];
__device__ bf16 g_k_h[BT * DM], g_k_l[BT * DM];
__device__ bf16 g_v_h[BT * DM], g_v_l[BT * DM];
// split-bf16 weights, all stored [N][K] (K contiguous)
__device__ bf16 g_wq_h[NL * D3 * DM], g_wq_l[NL * D3 * DM];
__device__ bf16 g_wp_h[NL * DM * DM], g_wp_l[NL * DM * DM];
__device__ bf16 g_wf_h[NL * D4 * DM], g_wf_l[NL * D4 * DM];
__device__ bf16 g_wW_h[NL * D4 * D4], g_wW_l[NL * D4 * D4];
__device__ bf16 g_wV_h[NL * D4 * D4], g_wV_l[NL * D4 * D4];
__device__ bf16 g_wm_h[NL * DM * D4], g_wm_l[NL * DM * D4];

// ================= asm helpers (base sm_103 features only) =================
__device__ __forceinline__ uint32_t smem_u32(const void* p) {
    uint32_t a;
    asm("{ .reg .u64 t; cvta.to.shared.u64 t, %1; cvt.u32.u64 %0, t; }" : "=r"(a) : "l"(p));
    return a;
}
__device__ __forceinline__ float fexp2(float x) {
    float r;
    asm("ex2.approx.ftz.f32 %0, %1;" : "=f"(r) : "f"(x));
    return r;
}
#define SWZ(off) ((off) ^ (((off) >> 3) & 0x70))

#define CP16(dst, src) \
    asm volatile("cp.async.cg.shared.global [%0], [%1], 16;" :: "r"(dst), "l"(src) : "memory")
#define CP_COMMIT() asm volatile("cp.async.commit_group;" ::: "memory")
#define CP_WAIT1()  asm volatile("cp.async.wait_group 1;"  ::: "memory")
#define CP_WAIT0()  asm volatile("cp.async.wait_group 0;"  ::: "memory")

#define LDM4(r0, r1, r2, r3, addr) \
    asm volatile("ldmatrix.sync.aligned.m8n8.x4.shared.b16 {%0,%1,%2,%3}, [%4];" \
                 : "=r"(r0), "=r"(r1), "=r"(r2), "=r"(r3) : "r"(addr))

#define LDM4T(r0, r1, r2, r3, addr) \
    asm volatile("ldmatrix.sync.aligned.m8n8.x4.trans.shared.b16 {%0,%1,%2,%3}, [%4];" \
                 : "=r"(r0), "=r"(r1), "=r"(r2), "=r"(r3) : "r"(addr))

#define MMA(D, A, B) \
    asm volatile("mma.sync.aligned.m16n8k16.row.col.f32.bf16.bf16.f32 " \
                 "{%0,%1,%2,%3}, {%4,%5,%6,%7}, {%8,%9}, {%0,%1,%2,%3};" \
                 : "+f"((D)[0]), "+f"((D)[1]), "+f"((D)[2]), "+f"((D)[3]) \
                 : "r"((A)[0]), "r"((A)[1]), "r"((A)[2]), "r"((A)[3]), \
                   "r"((B)[0]), "r"((B)[1]))

__device__ __forceinline__ void split2_store(bf16* H, bf16* L, size_t off, float v0, float v1) {
    bf16 h0 = __float2bfloat16(v0), h1 = __float2bfloat16(v1);
    bf16 l0 = __float2bfloat16(v0 - __bfloat162float(h0));
    bf16 l1 = __float2bfloat16(v1 - __bfloat162float(h1));
    *(__nv_bfloat162*)(H + off) = __halves2bfloat162(h0, h1);
    *(__nv_bfloat162*)(L + off) = __halves2bfloat162(l0, l1);
}

__device__ __forceinline__ void splitpack(float x, float y, uint32_t& hi, uint32_t& lo) {
    bf16 xh = __float2bfloat16(x), yh = __float2bfloat16(y);
    bf16 xl = __float2bfloat16(x - __bfloat162float(xh));
    bf16 yl = __float2bfloat16(y - __bfloat162float(yh));
    hi = (uint32_t)__bfloat16_as_ushort(xh) | ((uint32_t)__bfloat16_as_ushort(yh) << 16);
    lo = (uint32_t)__bfloat16_as_ushort(xl) | ((uint32_t)__bfloat16_as_ushort(yl) << 16);
}

// ---------------- weight conversion ----------------
__global__ void split_all(const float* __restrict__ s0, bf16* h0, bf16* l0, int n0,
                          const float* __restrict__ s1, bf16* h1, bf16* l1, int n1,
                          const float* __restrict__ s2, bf16* h2, bf16* l2, int n2,
                          const float* __restrict__ s3, bf16* h3, bf16* l3, int n3) {
    const float* s; bf16 *h, *l; int n;
    switch (blockIdx.y) {
        case 0: s = s0; h = h0; l = l0; n = n0; break;
        case 1: s = s1; h = h1; l = l1; n = n1; break;
        case 2: s = s2; h = h2; l = l2; n = n2; break;
        default:s = s3; h = h3; l = l3; n = n3; break;
    }
    int i = blockIdx.x * blockDim.x + threadIdx.x;
    if (i >= n) return;
    float4 v = ((const float4*)s)[i];
    split2_store(h, l, (size_t)i * 4,     v.x, v.y);
    split2_store(h, l, (size_t)i * 4 + 2, v.z, v.w);
}

__global__ void transpose_all(const float* __restrict__ W, const float* __restrict__ V,
                              bf16* __restrict__ Wh, bf16* __restrict__ Wl,
                              bf16* __restrict__ Vh, bf16* __restrict__ Vl) {
    __shared__ float t[32][33];
    int z = blockIdx.z;
    int l = (z < NL) ? z : z - NL;
    const float* s = ((z < NL) ? W : V) + (size_t)l * D4 * D4;
    bf16* H = ((z < NL) ? Wh : Vh) + (size_t)l * D4 * D4;
    bf16* L = ((z < NL) ? Wl : Vl) + (size_t)l * D4 * D4;
    int n0 = blockIdx.x * 32, k0 = blockIdx.y * 32;
    int cx = threadIdx.x;
    #pragma unroll
    for (int r = threadIdx.y; r < 32; r += 8)
        t[r][cx] = s[(size_t)(k0 + r) * D4 + n0 + cx];
    __syncthreads();
    #pragma unroll
    for (int r = threadIdx.y; r < 32; r += 8) {
        float v = t[cx][r];
        size_t off = (size_t)(n0 + r) * D4 + k0 + cx;
        bf16 h = __float2bfloat16(v);
        H[off] = h;
        L[off] = __float2bfloat16(v - __bfloat162float(h));
    }
}

// ---------------- qkv fp32 -> pre-split q/k/v bf16 ----------------
__global__ void qkv_split(const float* __restrict__ qkv,
                          bf16* __restrict__ qh, bf16* __restrict__ ql,
                          bf16* __restrict__ kh, bf16* __restrict__ kl,
                          bf16* __restrict__ vh, bf16* __restrict__ vl) {
    int i = blockIdx.x * blockDim.x + threadIdx.x;
    const int per_row = D3 / 4;
    int bt = i / per_row, c4 = (i % per_row) * 4;
    float4 v = *(const float4*)&qkv[(size_t)bt * D3 + c4];
    bf16 *H, *L; int cc;
    if (c4 < DM)          { H = qh; L = ql; cc = c4; }
    else if (c4 < 2 * DM) { H = kh; L = kl; cc = c4 - DM; }
    else                  { H = vh; L = vl; cc = c4 - 2 * DM; }
    size_t off = (size_t)bt * DM + cc;
    split2_store(H, L, off,     v.x, v.y);
    split2_store(H, L, off + 2, v.z, v.w);
}

// ---------------- embedding ----------------
__global__ void embed_kernel(const int* __restrict__ idx, const float* __restrict__ wte,
                             const float* __restrict__ wpe, float* __restrict__ x) {
    int bt = blockIdx.x;
    int t  = bt & (TT - 1);
    int tok = idx[bt];
    int c = threadIdx.x * 4;
    float4 a = *(const float4*)&wte[(size_t)tok * DM + c];
    float4 p = *(const float4*)&wpe[(size_t)t   * DM + c];
    a.x += p.x; a.y += p.y; a.z += p.z; a.w += p.w;
    *(float4*)&x[(size_t)bt * DM + c] = a;
}

// ---------------- split-K partial reduce: x += p0 + p1 ----------------
__global__ void addparts(float* __restrict__ x, const float* __restrict__ p, int n4) {
    int i = blockIdx.x * blockDim.x + threadIdx.x;
    if (i >= n4) return;
    float4 xv = ((const float4*)x)[i];
    float4 a = ((const float4*)p)[i];
    float4 b = ((const float4*)(p + (size_t)BT * DM))[i];
    xv.x += a.x + b.x; xv.y += a.y + b.y; xv.z += a.z + b.z; xv.w += a.w + b.w;
    ((float4*)x)[i] = xv;
}

// ---------------- elementwise swiglu + split ----------------
__global__ void swiglu_split(const float* __restrict__ a, const float* __restrict__ c2f,
                             bf16* __restrict__ H, bf16* __restrict__ L, int n4) {
    int i = blockIdx.x * blockDim.x + threadIdx.x;
    if (i >= n4) return;
    float4 g = ((const float4*)a)[i];
    float4 v = ((const float4*)c2f)[i];
    float o0 = g.x / (1.f + __expf(-g.x)) * v.x;
    float o1 = g.y / (1.f + __expf(-g.y)) * v.y;
    float o2 = g.z / (1.f + __expf(-g.z)) * v.z;
    float o3 = g.w / (1.f + __expf(-g.w)) * v.w;
    split2_store(H, L, (size_t)i * 4,     o0, o1);
    split2_store(H, L, (size_t)i * 4 + 2, o2, o3);
}

// ---------------- layernorm (plain) ----------------
template <bool SPLIT>
__global__ __launch_bounds__(256)
void ln_kernel(const float* __restrict__ x, size_t rstride,
               const float* __restrict__ w, const float* __restrict__ b,
               float* __restrict__ yf, bf16* __restrict__ yh, bf16* __restrict__ yl) {
    const float* xr = x + (size_t)blockIdx.x * rstride;
    int tid = threadIdx.x;

    float v0 = xr[tid], v1 = xr[tid + 256], v2 = xr[tid + 512];
    float s  = v0 + v1 + v2;
    float s2 = v0 * v0 + v1 * v1 + v2 * v2;
    #pragma unroll
    for (int off = 16; off; off >>= 1) {
        s  += __shfl_xor_sync(0xffffffffu, s,  off);
        s2 += __shfl_xor_sync(0xffffffffu, s2, off);
    }
    __shared__ float sh_s[8], sh_s2[8];
    int wid = tid >> 5, lane = tid & 31;
    if (lane == 0) { sh_s[wid] = s; sh_s2[wid] = s2; }
    __syncthreads();
    float tot = 0.f, tot2 = 0.f;
    #pragma unroll
    for (int i = 0; i < 8; i++) { tot += sh_s[i]; tot2 += sh_s2[i]; }
    const float inv = 1.0f / (float)DM;
    float mean = tot * inv;
    float var  = tot2 * inv - mean * mean;
    float rstd = rsqrtf(var + 1e-5f);

    size_t base = (size_t)blockIdx.x * DM;
    float o0 = (v0 - mean) * rstd * w[tid]       + b[tid];
    float o1 = (v1 - mean) * rstd * w[tid + 256] + b[tid + 256];
    float o2 = (v2 - mean) * rstd * w[tid + 512] + b[tid + 512];
    if (SPLIT) {
        bf16 h0 = __float2bfloat16(o0);
        yh[base + tid] = h0;       yl[base + tid]       = __float2bfloat16(o0 - __bfloat162float(h0));
        bf16 h1 = __float2bfloat16(o1);
        yh[base + tid + 256] = h1; yl[base + tid + 256] = __float2bfloat16(o1 - __bfloat162float(h1));
        bf16 h2 = __float2bfloat16(o2);
        yh[base + tid + 512] = h2; yl[base + tid + 512] = __float2bfloat16(o2 - __bfloat162float(h2));
    } else {
        yf[base + tid]       = o0;
        yf[base + tid + 256] = o1;
        yf[base + tid + 512] = o2;
    }
}

// ---------------- fused residual-add + layernorm-split ----------------
// x = x + p0 + p1 (written back); (yh,yl) = split(LN(x))
__global__ __launch_bounds__(256)
void lnadd_kernel(float* __restrict__ x, const float* __restrict__ p,
                  const float* __restrict__ w, const float* __restrict__ b,
                  bf16* __restrict__ yh, bf16* __restrict__ yl) {
    size_t base = (size_t)blockIdx.x * DM;
    int tid = threadIdx.x;
    const float* p1 = p + (size_t)BT * DM;

    float v0 = x[base + tid]       + p[base + tid]       + p1[base + tid];
    float v1 = x[base + tid + 256] + p[base + tid + 256] + p1[base + tid + 256];
    float v2 = x[base + tid + 512] + p[base + tid + 512] + p1[base + tid + 512];
    x[base + tid]       = v0;
    x[base + tid + 256] = v1;
    x[base + tid + 512] = v2;

    float s  = v0 + v1 + v2;
    float s2 = v0 * v0 + v1 * v1 + v2 * v2;
    #pragma unroll
    for (int off = 16; off; off >>= 1) {
        s  += __shfl_xor_sync(0xffffffffu, s,  off);
        s2 += __shfl_xor_sync(0xffffffffu, s2, off);
    }
    __shared__ float sh_s[8], sh_s2[8];
    int wid = tid >> 5, lane = tid & 31;
    if (lane == 0) { sh_s[wid] = s; sh_s2[wid] = s2; }
    __syncthreads();
    float tot = 0.f, tot2 = 0.f;
    #pragma unroll
    for (int i = 0; i < 8; i++) { tot += sh_s[i]; tot2 += sh_s2[i]; }
    const float inv = 1.0f / (float)DM;
    float mean = tot * inv;
    float var  = tot2 * inv - mean * mean;
    float rstd = rsqrtf(var + 1e-5f);

    float o0 = (v0 - mean) * rstd * w[tid]       + b[tid];
    float o1 = (v1 - mean) * rstd * w[tid + 256] + b[tid + 256];
    float o2 = (v2 - mean) * rstd * w[tid + 512] + b[tid + 512];
    bf16 h0 = __float2bfloat16(o0);
    yh[base + tid] = h0;       yl[base + tid]       = __float2bfloat16(o0 - __bfloat162float(h0));
    bf16 h1 = __float2bfloat16(o1);
    yh[base + tid + 256] = h1; yl[base + tid + 256] = __float2bfloat16(o1 - __bfloat162float(h1));
    bf16 h2 = __float2bfloat16(o2);
    yh[base + tid + 512] = h2; yl[base + tid + 512] = __float2bfloat16(o2 - __bfloat162float(h2));
}

// ================= mma.sync split-bf16 GEMM =================
#define GM_F32    0
#define GM_RES    1
#define GM_SPLIT  2
#define GM_PART   3
#define GM_DUAL   4

#define GSTAGE 65536
#define GSMEM  (3 * GSTAGE + 1024)

struct Frags {
    uint32_t aH[2][4], aL[2][4], bH[8][2], bL[8][2];
};

template <int MODE>
__global__ __launch_bounds__(256, 1)
void gemm_mma(const bf16* __restrict__ Ah, const bf16* __restrict__ Al,
              const bf16* __restrict__ Bh, const bf16* __restrict__ Bl,
              const float* __restrict__ bias,
              float* __restrict__ Cf, bf16* __restrict__ Ch, bf16* __restrict__ Cl,
              const bf16* __restrict__ B2h, const bf16* __restrict__ B2l,
              const float* __restrict__ bias2, float* __restrict__ Cf2,
              int N, int K, int lda) {
    extern __shared__ char dyn[];
    uint32_t base = (smem_u32(dyn) + 1023) & ~1023u;

    const int tid = threadIdx.x;
    const int bm = blockIdx.y * 128, bn = blockIdx.x * 128;
    const int koff = (MODE == GM_PART) ? blockIdx.z * K : 0;
    const int lane = tid & 31, wid = tid >> 5;
    const int wm = wid & 3, wn = wid >> 2;

    const bf16* Bh_ = Bh;
    const bf16* Bl_ = Bl;
    const float* bias_ = bias;
    float* Cf_ = Cf;
    if (MODE == GM_DUAL && blockIdx.z) { Bh_ = B2h; Bl_ = B2l; bias_ = bias2; Cf_ = Cf2; }

    const int lr = ((lane >> 3) & 1) * 8 + (lane & 7);
    const int lk = lane >> 4;

    float d[2][8][4];
    #pragma unroll
    for (int i = 0; i < 2; i++)
        #pragma unroll
        for (int j = 0; j < 8; j++)
            #pragma unroll
            for (int q = 0; q < 4; q++) d[i][j][q] = 0.f;

    const int nkt = K >> 6;

    auto load_stage = [&](int kt, int sb) {
        uint32_t st = base + sb * GSTAGE;
        int k0 = koff + (kt << 6);
        #pragma unroll
        for (int i = 0; i < 4; i++) {
            int row = (tid >> 3) + i * 32;
            int seg = tid & 7;
            uint32_t soff = SWZ(row * 128 + seg * 16);
            size_t ga = (size_t)(bm + row) * lda + k0 + seg * 8;
            size_t gb = (size_t)(bn + row) * lda + k0 + seg * 8;
            CP16(st + soff,         Ah + ga);
            CP16(st + 16384 + soff, Al + ga);
            CP16(st + 32768 + soff, Bh_ + gb);
            CP16(st + 49152 + soff, Bl_ + gb);
        }
    };

    auto load_frags = [&](uint32_t st, int ks, Frags& f) {
        #pragma unroll
        for (int am = 0; am < 2; am++) {
            int row = wm * 32 + am * 16 + lr;
            uint32_t off = SWZ(row * 128 + (ks * 2 + lk) * 16);
            LDM4(f.aH[am][0], f.aH[am][1], f.aH[am][2], f.aH[am][3], st + off);
            LDM4(f.aL[am][0], f.aL[am][1], f.aL[am][2], f.aL[am][3], st + 16384 + off);
        }
        #pragma unroll
        for (int nb = 0; nb < 4; nb++) {
            int row = wn * 64 + nb * 16 + lr;
            uint32_t off = SWZ(row * 128 + (ks * 2 + lk) * 16);
            uint32_t t0, t1, t2, t3;
            LDM4(t0, t1, t2, t3, st + 32768 + off);
            f.bH[2*nb][0] = t0; f.bH[2*nb][1] = t2; f.bH[2*nb+1][0] = t1; f.bH[2*nb+1][1] = t3;
            LDM4(t0, t1, t2, t3, st + 49152 + off);
            f.bL[2*nb][0] = t0; f.bL[2*nb][1] = t2; f.bL[2*nb+1][0] = t1; f.bL[2*nb+1][1] = t3;
        }
    };
    auto do_mma = [&](Frags& f) {
        #pragma unroll
        for (int am = 0; am < 2; am++)
            #pragma unroll
            for (int an = 0; an < 8; an++) {
                MMA(d[am][an], f.aH[am], f.bH[an]);
                MMA(d[am][an], f.aH[am], f.bL[an]);
                MMA(d[am][an], f.aL[am], f.bH[an]);
            }
    };

    load_stage(0, 0); CP_COMMIT();
    load_stage(1, 1); CP_COMMIT();

    Frags fr[2];
    for (int kt = 0; kt < nkt; kt++) {
        CP_WAIT1();
        __syncthreads();
        if (kt + 2 < nkt) load_stage(kt + 2, (kt + 2) % 3);
        CP_COMMIT();

        uint32_t st = base + (kt % 3) * GSTAGE;
        load_frags(st, 0, fr[0]);
        #pragma unroll
        for (int ks = 0; ks < 4; ks++) {
            if (ks < 3) load_frags(st, ks + 1, fr[(ks + 1) & 1]);
            do_mma(fr[ks & 1]);
        }
    }

    const int g = lane >> 2, tq = lane & 3;
    #pragma unroll
    for (int am = 0; am < 2; am++)
        #pragma unroll
        for (int an = 0; an < 8; an++) {
            int r0 = bm + wm * 32 + am * 16 + g;
            int c  = bn + wn * 64 + an * 8 + tq * 2;
            #pragma unroll
            for (int half = 0; half < 2; half++) {
                int row = r0 + half * 8;
                float v0 = d[am][an][half * 2];
                float v1 = d[am][an][half * 2 + 1];
                if (MODE != GM_PART || blockIdx.z == 0) { v0 += bias_[c]; v1 += bias_[c + 1]; }
                size_t off = (size_t)row * N + c;
                if (MODE == GM_F32 || MODE == GM_DUAL) {
                    *(float2*)(Cf_ + off) = make_float2(v0, v1);
                } else if (MODE == GM_RES) {
                    float2 o = *(const float2*)(Cf_ + off);
                    *(float2*)(Cf_ + off) = make_float2(v0 + o.x, v1 + o.y);
                } else if (MODE == GM_SPLIT) {
                    split2_store(Ch, Cl, off, v0, v1);
                } else {  // GM_PART
                    *(float2*)(Cf_ + (size_t)blockIdx.z * BT * DM + off) = make_float2(v0, v1);
                }
            }
        }
}

// ---------------- SIMT sgemm (lm_head only, M=4) ----------------
__global__ __launch_bounds__(256)
void sgemm_kernel(const float* __restrict__ A, const float* __restrict__ B,
                  float* __restrict__ C, int M, int N, int K) {
    __shared__ float As[8 * 128];
    __shared__ float Bs[8 * 128];

    const int tid = threadIdx.x;
    const int tx = tid & 15, ty = tid >> 4;
    const int bm = blockIdx.y * 128, bn = blockIdx.x * 128;

    float acc[8][8];
    #pragma unroll
    for (int i = 0; i < 8; i++)
        #pragma unroll
        for (int j = 0; j < 8; j++) acc[i][j] = 0.f;

    const int arow = tid >> 1;
    const int acol = (tid & 1) * 4;

    for (int k0 = 0; k0 < K; k0 += 8) {
        float4 av = make_float4(0.f, 0.f, 0.f, 0.f);
        if (bm + arow < M)
            av = *(const float4*)&A[(size_t)(bm + arow) * K + k0 + acol];
        As[(acol + 0) * 128 + arow] = av.x;
        As[(acol + 1) * 128 + arow] = av.y;
        As[(acol + 2) * 128 + arow] = av.z;
        As[(acol + 3) * 128 + arow] = av.w;
        float4 bv = *(const float4*)&B[(size_t)(bn + arow) * K + k0 + acol];
        Bs[(acol + 0) * 128 + arow] = bv.x;
        Bs[(acol + 1) * 128 + arow] = bv.y;
        Bs[(acol + 2) * 128 + arow] = bv.z;
        Bs[(acol + 3) * 128 + arow] = bv.w;
        __syncthreads();

        #pragma unroll
        for (int kk = 0; kk < 8; kk++) {
            float a[8], b[8];
            *(float4*)&a[0] = *(const float4*)&As[kk * 128 + ty * 8];
            *(float4*)&a[4] = *(const float4*)&As[kk * 128 + ty * 8 + 4];
            *(float4*)&b[0] = *(const float4*)&Bs[kk * 128 + tx * 8];
            *(float4*)&b[4] = *(const float4*)&Bs[kk * 128 + tx * 8 + 4];
            #pragma unroll
            for (int i = 0; i < 8; i++)
                #pragma unroll
                for (int j = 0; j < 8; j++)
                    acc[i][j] = fmaf(a[i], b[j], acc[i][j]);
        }
        __syncthreads();
    }

    #pragma unroll
    for (int i = 0; i < 8; i++) {
        int row = bm + ty * 8 + i;
        if (row >= M) continue;
        #pragma unroll
        for (int j = 0; j < 8; j++)
            C[(size_t)row * N + bn + tx * 8 + j] = acc[i][j];
    }
}

// ================= HMMA flash attention (pre-split q/k/v, KV double-buffered) =======
#define ATSM (16384 + 2 * 32768)   // Q(16KB) + 2 KV stages (32KB each) = 80KB

__global__ __launch_bounds__(128)
void attn_mma(const bf16* __restrict__ qh, const bf16* __restrict__ ql,
              const bf16* __restrict__ kh, const bf16* __restrict__ kl,
              const bf16* __restrict__ vh, const bf16* __restrict__ vl,
              bf16* __restrict__ oh, bf16* __restrict__ ol) {
    extern __shared__ char smn[];
    const uint32_t uq_h = smem_u32(smn);
    const uint32_t uq_l = uq_h + 8192;

    const int tid = threadIdx.x;
    const int lane = tid & 31, w = tid >> 5;
    const int qi = blockIdx.x;
    const int b = blockIdx.y / NHEAD, h = blockIdx.y % NHEAD;
    const int lr = ((lane >> 3) & 1) * 8 + (lane & 7);
    const int lk = lane >> 4;
    const int g = lane >> 2, tq = lane & 3;
    const int gi = lane >> 3;
    const int pv_row = ((gi >> 1) & 1) * 8 + (lane & 7);
    const int pv_col = (gi & 1) * 8;

    const float SC = 0.18033688011112042f;   // 0.125 * log2(e)

    auto load_kv = [&](int kt, int sb) {
        uint32_t st = uq_h + 16384 + sb * 32768;   // kh@0 kl@8192 vh@16384 vl@24576
        #pragma unroll
        for (int it = 0; it < 4; it++) {
            int i = tid + it * 128;
            int row = i >> 3, seg = i & 7;
            uint32_t off = SWZ(row * 128 + seg * 16);
            size_t gg = (size_t)(b * TT + kt * 64 + row) * DM + h * HDIM + seg * 8;
            CP16(st + off,         kh + gg);
            CP16(st + 8192 + off,  kl + gg);
            CP16(st + 16384 + off, vh + gg);
            CP16(st + 24576 + off, vl + gg);
        }
    };

    // ---- Q tile ----
    #pragma unroll
    for (int it = 0; it < 4; it++) {
        int i = tid + it * 128;
        int row = i >> 3, seg = i & 7;
        uint32_t off = SWZ(row * 128 + seg * 16);
        size_t gq = (size_t)(b * TT + qi * 64 + row) * DM + h * HDIM + seg * 8;
        CP16(uq_h + off, qh + gq);
        CP16(uq_l + off, ql + gq);
    }
    CP_COMMIT();              // group: Q
    load_kv(0, 0);
    CP_COMMIT();              // group: kv0
    CP_WAIT1();               // Q done
    __syncthreads();

    uint32_t qAh[4][4], qAl[4][4];
    #pragma unroll
    for (int kk = 0; kk < 4; kk++) {
        uint32_t off = SWZ((w * 16 + lr) * 128 + (kk * 2 + lk) * 16);
        LDM4(qAh[kk][0], qAh[kk][1], qAh[kk][2], qAh[kk][3], uq_h + off);
        LDM4(qAl[kk][0], qAl[kk][1], qAl[kk][2], qAl[kk][3], uq_l + off);
    }

    float m0 = -1e30f, m1 = -1e30f, l0 = 0.f, l1 = 0.f;
    float o[8][4];
    #pragma unroll
    for (int j = 0; j < 8; j++)
        #pragma unroll
        for (int q = 0; q < 4; q++) o[j][q] = 0.f;

    const int rg0 = qi * 64 + w * 16 + g;

    for (int kt = 0; kt <= qi; kt++) {
        if (kt < qi) { load_kv(kt + 1, (kt + 1) & 1); CP_COMMIT(); CP_WAIT1(); }
        else         { CP_WAIT0(); }
        __syncthreads();   // stage kt data visible to all threads

        uint32_t st  = uq_h + 16384 + (kt & 1) * 32768;
        uint32_t ukh = st, ukl = st + 8192, uvh = st + 16384, uvl = st + 24576;

        float s[8][4];
        #pragma unroll
        for (int j = 0; j < 8; j++)
            #pragma unroll
            for (int q = 0; q < 4; q++) s[j][q] = 0.f;

        #pragma unroll
        for (int kk = 0; kk < 4; kk++) {
            uint32_t th[4][4], tl[4][4];
            #pragma unroll
            for (int nb = 0; nb < 4; nb++) {
                uint32_t off = SWZ((nb * 16 + lr) * 128 + (kk * 2 + lk) * 16);
                LDM4(th[nb][0], th[nb][1], th[nb][2], th[nb][3], ukh + off);
                LDM4(tl[nb][0], tl[nb][1], tl[nb][2], tl[nb][3], ukl + off);
            }
            #pragma unroll
            for (int nb = 0; nb < 4; nb++) {
                uint32_t B0h[2] = {th[nb][0], th[nb][2]};
                uint32_t B1h[2] = {th[nb][1], th[nb][3]};
                uint32_t B0l[2] = {tl[nb][0], tl[nb][2]};
                uint32_t B1l[2] = {tl[nb][1], tl[nb][3]};
                MMA(s[2*nb],   qAh[kk], B0h);
                MMA(s[2*nb],   qAh[kk], B0l);
                MMA(s[2*nb],   qAl[kk], B0h);
                MMA(s[2*nb+1], qAh[kk], B1h);
                MMA(s[2*nb+1], qAh[kk], B1l);
                MMA(s[2*nb+1], qAl[kk], B1h);
            }
        }

        #pragma unroll
        for (int j = 0; j < 8; j++) {
            s[j][0] *= SC; s[j][1] *= SC; s[j][2] *= SC; s[j][3] *= SC;
        }
        if (kt == qi) {
            #pragma unroll
            for (int j = 0; j < 8; j++) {
                int col = kt * 64 + j * 8 + tq * 2;
                if (col     > rg0)     s[j][0] = -1e30f;
                if (col + 1 > rg0)     s[j][1] = -1e30f;
                if (col     > rg0 + 8) s[j][2] = -1e30f;
                if (col + 1 > rg0 + 8) s[j][3] = -1e30f;
            }
        }

        float mt0 = -1e30f, mt1 = -1e30f;
        #pragma unroll
        for (int j = 0; j < 8; j++) {
            mt0 = fmaxf(mt0, fmaxf(s[j][0], s[j][1]));
            mt1 = fmaxf(mt1, fmaxf(s[j][2], s[j][3]));
        }
        mt0 = fmaxf(mt0, __shfl_xor_sync(0xffffffffu, mt0, 1));
        mt0 = fmaxf(mt0, __shfl_xor_sync(0xffffffffu, mt0, 2));
        mt1 = fmaxf(mt1, __shfl_xor_sync(0xffffffffu, mt1, 1));
        mt1 = fmaxf(mt1, __shfl_xor_sync(0xffffffffu, mt1, 2));
        float mn0 = fmaxf(m0, mt0), mn1 = fmaxf(m1, mt1);
        float a0 = fexp2(m0 - mn0), a1 = fexp2(m1 - mn1);
        m0 = mn0; m1 = mn1;

        float sum0 = 0.f, sum1 = 0.f;
        #pragma unroll
        for (int j = 0; j < 8; j++) {
            s[j][0] = fexp2(s[j][0] - mn0);
            s[j][1] = fexp2(s[j][1] - mn0);
            s[j][2] = fexp2(s[j][2] - mn1);
            s[j][3] = fexp2(s[j][3] - mn1);
            sum0 += s[j][0] + s[j][1];
            sum1 += s[j][2] + s[j][3];
        }
        sum0 += __shfl_xor_sync(0xffffffffu, sum0, 1);
        sum0 += __shfl_xor_sync(0xffffffffu, sum0, 2);
        sum1 += __shfl_xor_sync(0xffffffffu, sum1, 1);
        sum1 += __shfl_xor_sync(0xffffffffu, sum1, 2);
        l0 = l0 * a0 + sum0;
        l1 = l1 * a1 + sum1;
        #pragma unroll
        for (int j = 0; j < 8; j++) {
            o[j][0] *= a0; o[j][1] *= a0; o[j][2] *= a1; o[j][3] *= a1;
        }

        uint32_t pH[4][4], pL[4][4];
        #pragma unroll
        for (int kk = 0; kk < 4; kk++) {
            splitpack(s[2*kk][0],   s[2*kk][1],   pH[kk][0], pL[kk][0]);
            splitpack(s[2*kk][2],   s[2*kk][3],   pH[kk][1], pL[kk][1]);
            splitpack(s[2*kk+1][0], s[2*kk+1][1], pH[kk][2], pL[kk][2]);
            splitpack(s[2*kk+1][2], s[2*kk+1][3], pH[kk][3], pL[kk][3]);
        }

        #pragma unroll
        for (int kk = 0; kk < 4; kk++) {
            uint32_t th[4][4], tl[4][4];
            #pragma unroll
            for (int nb = 0; nb < 4; nb++) {
                uint32_t off = SWZ((kk * 16 + pv_row) * 128 + (nb * 16 + pv_col) * 2);
                LDM4T(th[nb][0], th[nb][1], th[nb][2], th[nb][3], uvh + off);
                LDM4T(tl[nb][0], tl[nb][1], tl[nb][2], tl[nb][3], uvl + off);
            }
            #pragma unroll
            for (int nb = 0; nb < 4; nb++) {
                uint32_t B0h[2] = {th[nb][0], th[nb][2]};
                uint32_t B1h[2] = {th[nb][1], th[nb][3]};
                uint32_t B0l[2] = {tl[nb][0], tl[nb][2]};
                uint32_t B1l[2] = {tl[nb][1], tl[nb][3]};
                MMA(o[2*nb],   pH[kk], B0h);
                MMA(o[2*nb],   pH[kk], B0l);
                MMA(o[2*nb],   pL[kk], B0h);
                MMA(o[2*nb+1], pH[kk], B1h);
                MMA(o[2*nb+1], pH[kk], B1l);
                MMA(o[2*nb+1], pL[kk], B1h);
            }
        }
        __syncthreads();   // all reads of this stage done before it is overwritten
    }

    float i0 = 1.f / l0, i1 = 1.f / l1;
    size_t r0 = (size_t)(b * TT + qi * 64 + w * 16 + g);
    #pragma unroll
    for (int j = 0; j < 8; j++) {
        int col = h * HDIM + j * 8 + tq * 2;
        split2_store(oh, ol, r0 * DM + col,       o[j][0] * i0, o[j][1] * i0);
        split2_store(oh, ol, (r0 + 8) * DM + col, o[j][2] * i1, o[j][3] * i1);
    }
}

// ---------------- launcher ----------------
extern "C" void kernel_launch(void* const* d_in, const int* in_sizes, int n_in,
                              void* d_out, int out_size) {
    const int*   idx    = (const int*)  d_in[0];
    const float* wte    = (const float*)d_in[1];
    const float* wpe    = (const float*)d_in[2];
    const float* ln1_w  = (const float*)d_in[3];
    const float* ln1_b  = (const float*)d_in[4];
    const float* caw    = (const float*)d_in[5];
    const float* cab    = (const float*)d_in[6];
    const float* cpw    = (const float*)d_in[7];
    const float* cpb    = (const float*)d_in[8];
    const float* ln2_w  = (const float*)d_in[9];
    const float* ln2_b  = (const float*)d_in[10];
    const float* cfw    = (const float*)d_in[11];
    const float* cfb    = (const float*)d_in[12];
    const float* swW    = (const float*)d_in[13];
    const float* swV    = (const float*)d_in[14];
    const float* swb    = (const float*)d_in[15];
    const float* swc    = (const float*)d_in[16];
    const float* mpw    = (const float*)d_in[17];
    const float* mpb    = (const float*)d_in[18];
    const float* lnf_w  = (const float*)d_in[19];
    const float* lnf_b  = (const float*)d_in[20];
    const float* lmw    = (const float*)d_in[21];
    float* out = (float*)d_out;

    float *x, *qkv, *a, *c2f, *xf, *part;
    bf16 *xn_h, *xn_l, *att_h, *att_l, *h_h, *h_l, *c2_h, *c2_l;
    bf16 *q_h, *q_l, *k_h, *k_l, *v_h, *v_l;
    bf16 *wq_h, *wq_l, *wp_h, *wp_l, *wf_h, *wf_l, *wW_h, *wW_l, *wV_h, *wV_l, *wm_h, *wm_l;
    cudaGetSymbolAddress((void**)&x,    g_x);
    cudaGetSymbolAddress((void**)&qkv,  g_qkv);
    cudaGetSymbolAddress((void**)&a,    g_a);
    cudaGetSymbolAddress((void**)&c2f,  g_c2f);
    cudaGetSymbolAddress((void**)&xf,   g_xf);
    cudaGetSymbolAddress((void**)&part, g_part);
    cudaGetSymbolAddress((void**)&xn_h, g_xn_h);  cudaGetSymbolAddress((void**)&xn_l, g_xn_l);
    cudaGetSymbolAddress((void**)&att_h,g_att_h); cudaGetSymbolAddress((void**)&att_l,g_att_l);
    cudaGetSymbolAddress((void**)&h_h,  g_h_h);   cudaGetSymbolAddress((void**)&h_l,  g_h_l);
    cudaGetSymbolAddress((void**)&c2_h, g_c2_h);  cudaGetSymbolAddress((void**)&c2_l, g_c2_l);
    cudaGetSymbolAddress((void**)&q_h,  g_q_h);   cudaGetSymbolAddress((void**)&q_l,  g_q_l);
    cudaGetSymbolAddress((void**)&k_h,  g_k_h);   cudaGetSymbolAddress((void**)&k_l,  g_k_l);
    cudaGetSymbolAddress((void**)&v_h,  g_v_h);   cudaGetSymbolAddress((void**)&v_l,  g_v_l);
    cudaGetSymbolAddress((void**)&wq_h, g_wq_h);  cudaGetSymbolAddress((void**)&wq_l, g_wq_l);
    cudaGetSymbolAddress((void**)&wp_h, g_wp_h);  cudaGetSymbolAddress((void**)&wp_l, g_wp_l);
    cudaGetSymbolAddress((void**)&wf_h, g_wf_h);  cudaGetSymbolAddress((void**)&wf_l, g_wf_l);
    cudaGetSymbolAddress((void**)&wW_h, g_wW_h);  cudaGetSymbolAddress((void**)&wW_l, g_wW_l);
    cudaGetSymbolAddress((void**)&wV_h, g_wV_h);  cudaGetSymbolAddress((void**)&wV_l, g_wV_l);
    cudaGetSymbolAddress((void**)&wm_h, g_wm_h);  cudaGetSymbolAddress((void**)&wm_l, g_wm_l);

    cudaFuncSetAttribute(attn_mma, cudaFuncAttributeMaxDynamicSharedMemorySize, ATSM);
    cudaFuncSetAttribute(gemm_mma<GM_F32>,   cudaFuncAttributeMaxDynamicSharedMemorySize, GSMEM);
    cudaFuncSetAttribute(gemm_mma<GM_RES>,   cudaFuncAttributeMaxDynamicSharedMemorySize, GSMEM);
    cudaFuncSetAttribute(gemm_mma<GM_SPLIT>, cudaFuncAttributeMaxDynamicSharedMemorySize, GSMEM);
    cudaFuncSetAttribute(gemm_mma<GM_PART>,  cudaFuncAttributeMaxDynamicSharedMemorySize, GSMEM);
    cudaFuncSetAttribute(gemm_mma<GM_DUAL>,  cudaFuncAttributeMaxDynamicSharedMemorySize, GSMEM);

    split_all<<<dim3(9216, 4), 256>>>(
        caw, wq_h, wq_l, NL * D3 * DM / 4,
        cpw, wp_h, wp_l, NL * DM * DM / 4,
        cfw, wf_h, wf_l, NL * D4 * DM / 4,
        mpw, wm_h, wm_l, NL * DM * D4 / 4);

    embed_kernel<<<BT, 192>>>(idx, wte, wpe, x);
    ln_kernel<true><<<BT, 256>>>(x, DM, ln1_w, ln1_b, nullptr, xn_h, xn_l);  // layer 0 ln1

    for (int l = 0; l < NL; l++) {
        size_t oq = (size_t)l * D3 * DM, op = (size_t)l * DM * DM;
        size_t of = (size_t)l * D4 * DM, ow = (size_t)l * D4 * D4, om = (size_t)l * DM * D4;
        gemm_mma<GM_F32><<<dim3(D3 / 128, BT / 128), 256, GSMEM>>>(
            xn_h, xn_l, wq_h + oq, wq_l + oq, cab + l * D3, qkv, nullptr, nullptr,
            nullptr, nullptr, nullptr, nullptr, D3, DM, DM);
        qkv_split<<<BT * D3 / 4 / 256, 256>>>(qkv, q_h, q_l, k_h, k_l, v_h, v_l);
        attn_mma<<<dim3(TT / 64, BB * NHEAD), 128, ATSM>>>(
            q_h, q_l, k_h, k_l, v_h, v_l, att_h, att_l);
        // proj: split-K x2, then fused add+ln2
        gemm_mma<GM_PART><<<dim3(DM / 128, BT / 128, 2), 256, GSMEM>>>(
            att_h, att_l, wp_h + op, wp_l + op, cpb + l * DM, part, nullptr, nullptr,
            nullptr, nullptr, nullptr, nullptr, DM, DM / 2, DM);
        lnadd_kernel<<<BT, 256>>>(x, part, ln2_w + l * DM, ln2_b + l * DM, xn_h, xn_l);
        if (l == 0) {
            transpose_all<<<dim3(D4 / 32, D4 / 32, 2 * NL), dim3(32, 8)>>>(
                swW, swV, wW_h, wW_l, wV_h, wV_l);
        }
        gemm_mma<GM_SPLIT><<<dim3(D4 / 128, BT / 128), 256, GSMEM>>>(
            xn_h, xn_l, wf_h + of, wf_l + of, cfb + l * D4, nullptr, h_h, h_l,
            nullptr, nullptr, nullptr, nullptr, D4, DM, DM);
        gemm_mma<GM_DUAL><<<dim3(D4 / 128, BT / 128, 2), 256, GSMEM>>>(
            h_h, h_l, wW_h + ow, wW_l + ow, swb + l * D4, a, nullptr, nullptr,
            wV_h + ow, wV_l + ow, swc + l * D4, c2f, D4, D4, D4);
        swiglu_split<<<(BT * D4 / 4 + 255) / 256, 256>>>(a, c2f, c2_h, c2_l, BT * D4 / 4);
        // mlp_proj: split-K x2, then fused add+ln1(next) or plain add (last layer)
        gemm_mma<GM_PART><<<dim3(DM / 128, BT / 128, 2), 256, GSMEM>>>(
            c2_h, c2_l, wm_h + om, wm_l + om, mpb + l * DM, part, nullptr, nullptr,
            nullptr, nullptr, nullptr, nullptr, DM, D4 / 2, D4);
        if (l + 1 < NL) {
            lnadd_kernel<<<BT, 256>>>(x, part, ln1_w + (l + 1) * DM, ln1_b + (l + 1) * DM,
                                      xn_h, xn_l);
        } else {
            addparts<<<(BT * DM / 4 + 255) / 256, 256>>>(x, part, BT * DM / 4);
        }
    }

    ln_kernel<false><<<BB, 256>>>(x + (size_t)(TT - 1) * DM, (size_t)TT * DM,
                                  lnf_w, lnf_b, xf, nullptr, nullptr);
    sgemm_kernel<<<dim3(VV / 128, 1), 256>>>(xf, lmw, out, BB, VV, DM);
}